// round 13
// baseline (speedup 1.0000x reference)
#include <cuda_runtime.h>
#include <cuda_fp16.h>
#include <math.h>
#include <stdint.h>

// ---------------- problem constants ----------------
#define BQ     256
#define TT     100
#define NFEAT  64
#define VV     32
#define EE     8
#define HH     512
#define NCAT   16
#define NCONT  48
#define INLEN  176
#define INP    192        // padded K for input projection
#define GG     2048
#define MT     (BQ*TT)

// persist smem (bytes): Bs half[64][520] + Ha half[8][64][72] + Xs f32[2][64][68] + Gs f32[2][64][68]
#define P_BS_B   (64*520*2)                 // 66,560
#define P_HA_B   (8*64*72*2)                // 73,728
#define P_XS_B   (2*64*68*4)                // 34,816
#define P_GS_B   (2*64*68*4)                // 34,816
#define P_HA_OFF (P_BS_B)
#define P_XS_OFF (P_BS_B + P_HA_B)
#define P_GS_OFF (P_BS_B + P_HA_B + P_XS_B)
#define PERSIST_SMEM (P_BS_B + P_HA_B + P_XS_B + P_GS_B)   // 209,920 B

// GEMM smem: 4 stages x (A 128x40 + W 128x40) halves
#define ASTG_H   (128*40)
#define ASTG_B   (ASTG_H*2)                 // 10,240 B
#define GEMM_SMEM (4 * 2 * ASTG_B)          // 81,920 B

// ---------------- scratch ----------------
__device__ __half g_feat[MT * INP + 64];
__device__ __half g_seq0[MT * HH + 64];
__device__ __half g_seq1[MT * HH + 64];
__device__ float  g_xw  [(size_t)MT * GG];
__device__ __half g_WinT[HH * INP + 64];
__device__ __half g_WihR[2 * GG * HH];
__device__ __half g_WhhR[2 * GG * HH];
__device__ __half g_ht  [2 * BQ * HH];      // m-major h state, double buffered
__device__ unsigned g_cnt[4];               // per-m0-group barrier counters
__device__ unsigned g_gen[4];

// ---------------- helpers ----------------
__device__ __forceinline__ void mmah(float* d, const unsigned* a, const unsigned* b) {
    asm volatile("mma.sync.aligned.m16n8k16.row.col.f32.f16.f16.f32 "
                 "{%0,%1,%2,%3}, {%4,%5,%6,%7}, {%8,%9}, {%0,%1,%2,%3};"
                 : "+f"(d[0]), "+f"(d[1]), "+f"(d[2]), "+f"(d[3])
                 : "r"(a[0]), "r"(a[1]), "r"(a[2]), "r"(a[3]), "r"(b[0]), "r"(b[1]));
}

__device__ __forceinline__ void ldsm4(unsigned& r0, unsigned& r1, unsigned& r2, unsigned& r3,
                                      unsigned addr) {
    asm volatile("ldmatrix.sync.aligned.m8n8.x4.shared.b16 {%0,%1,%2,%3}, [%4];"
                 : "=r"(r0), "=r"(r1), "=r"(r2), "=r"(r3) : "r"(addr));
}

__device__ __forceinline__ void cpasync16(void* smem_dst, const void* gsrc) {
    unsigned s = (unsigned)__cvta_generic_to_shared(smem_dst);
    asm volatile("cp.async.cg.shared.global [%0], [%1], 16;" :: "r"(s), "l"(gsrc));
}
__device__ __forceinline__ void cpcommit() { asm volatile("cp.async.commit_group;" ::: "memory"); }
template<int N> __device__ __forceinline__ void cpwaitN() {
    asm volatile("cp.async.wait_group %0;" :: "n"(N) : "memory");
}

__device__ __forceinline__ float sigm(float x)     { return 1.f / (1.f + __expf(-x)); }
__device__ __forceinline__ float tanhfast(float x) { return 2.f / (1.f + __expf(-2.f * x)) - 1.f; }

__device__ __forceinline__ void bar_grp(int khalf) {
    if (khalf == 0) asm volatile("bar.sync 1, 128;" ::: "memory");
    else            asm volatile("bar.sync 2, 128;" ::: "memory");
}

// ---------------- small utility kernels ----------------
__global__ void k_transpose_win(const float* __restrict__ Win, __half* __restrict__ WinT)
{
    int idx = blockIdx.x * blockDim.x + threadIdx.x;   // over HH*INP
    if (idx >= HH * INP) return;
    int n = idx / INP, k = idx % INP;
    WinT[idx] = (k < INLEN) ? __float2half_rn(Win[k * HH + n]) : __float2half_rn(0.f);
}

__global__ void k_round2(const float* __restrict__ A, __half* __restrict__ RA,
                         const float* __restrict__ B, __half* __restrict__ RB)
{
    int i = blockIdx.x * blockDim.x + threadIdx.x;
    if (i < 2 * GG * HH) { RA[i] = __float2half_rn(A[i]); RB[i] = __float2half_rn(B[i]); }
}

__global__ void k_reset()
{
    int i = blockIdx.x * blockDim.x + threadIdx.x;
    if (i < BQ * HH) g_ht[i] = __float2half_rn(0.f);   // only buffer 0 is read at t=0
    if (i < 4) { g_cnt[i] = 0; g_gen[i] = 0; }
}

__global__ void k_build_feat(const float* __restrict__ x,
                             const float* __restrict__ mean,
                             const float* __restrict__ scale,
                             const float* __restrict__ emb,
                             __half* __restrict__ feat)
{
    int idx = blockIdx.x * blockDim.x + threadIdx.x;   // over MT*INP
    if (idx >= MT * INP) return;
    int c = idx % INP;
    int m = idx / INP;
    float v = 0.f;
    if (c < INLEN) {
        int blk = c / 11, r = c % 11;
        if (r < 8) {
            int k  = 4 * blk;
            int xi = (int)x[(size_t)m * NFEAT + k];
            v = emb[((size_t)blk * VV + xi) * EE + r];
        } else {
            int k = 4 * blk + (r - 7);
            v = (x[(size_t)m * NFEAT + k] - mean[k]) / scale[k];
        }
    }
    feat[idx] = __float2half_rn(v);
}

// ---------------- fp16 NT GEMM: 128x128 CTA, 16 warps of 32x32, BK=32(half), 4-stage ----
__device__ __forceinline__ void gemm_load_stage(__half* dstA, __half* dstW,
                                                const __half* A, const __half* W,
                                                int bm, int bn, int K, int k0, int tid)
{
    // 512 threads: one 16B transfer each for A and W
    int row = tid >> 2;             // 0..127
    int q   = (tid & 3) << 3;       // 0,8,16,24 halves
    cpasync16(dstA + row * 40 + q, A + (size_t)(bm + row) * K + k0 + q);
    cpasync16(dstW + row * 40 + q, W + (size_t)(bn + row) * K + k0 + q);
}

__global__ __launch_bounds__(512, 2)
void k_gemm_fp16(const __half* __restrict__ A, const __half* __restrict__ W,
                 const float* __restrict__ bias, void* __restrict__ Cv,
                 int M, int N, int K, int flags)   // bit0: relu, bit1: half output
{
    extern __shared__ __half smh[];
    __half* As = smh;                       // [4][128*40]
    __half* Ws = smh + 4 * ASTG_H;

    const int tid  = threadIdx.x;
    const int bm   = blockIdx.y * 128;
    const int bn   = blockIdx.x * 128;
    const int lane = tid & 31, warp = tid >> 5;
    const int wm   = (warp & 3) * 32;       // 4 m-warps, tile 32
    const int wn   = (warp >> 2) * 32;      // 4 n-warps, tile 32
    const int r    = lane >> 2, cq = lane & 3;
    const int NK   = K >> 5;                // K % 32 == 0, NK >= 3

    const unsigned sbg = (unsigned)__cvta_generic_to_shared(smh);
    const int arow = lane & 15;
    const int kA   = (lane & 16) ? 8 : 0;   // halves
    const int brow = (lane & 7) + ((lane & 16) ? 8 : 0);
    const int kB   = (lane & 8) ? 8 : 0;    // halves
    const unsigned aoff = ((wm + arow) * 40 + kA) * 2;
    const unsigned boff = ((wn + brow) * 40 + kB) * 2;

    float acc[2][4][4];
#pragma unroll
    for (int mt = 0; mt < 2; mt++)
#pragma unroll
        for (int in = 0; in < 4; in++)
#pragma unroll
            for (int q = 0; q < 4; q++) acc[mt][in][q] = 0.f;

    gemm_load_stage(As, Ws, A, W, bm, bn, K, 0, tid); cpcommit();
    gemm_load_stage(As + ASTG_H, Ws + ASTG_H, A, W, bm, bn, K, 32, tid); cpcommit();
    gemm_load_stage(As + 2 * ASTG_H, Ws + 2 * ASTG_H, A, W, bm, bn, K, 64, tid); cpcommit();

    for (int kc = 0; kc < NK; kc++) {
        if      (kc < NK - 2) cpwaitN<2>();
        else if (kc < NK - 1) cpwaitN<1>();
        else                  cpwaitN<0>();
        __syncthreads();
        if (kc + 3 < NK) {
            int s = (kc + 3) & 3;
            gemm_load_stage(As + s * ASTG_H, Ws + s * ASTG_H, A, W, bm, bn, K,
                            (kc + 3) << 5, tid);
            cpcommit();
        }
        const unsigned asb = sbg + (kc & 3) * ASTG_B;
        const unsigned wsb = sbg + 4 * ASTG_B + (kc & 3) * ASTG_B;
#pragma unroll
        for (int kk = 0; kk < 32; kk += 16) {
            unsigned a[2][4], b[4][2];
#pragma unroll
            for (int mt = 0; mt < 2; mt++)
                ldsm4(a[mt][0], a[mt][1], a[mt][2], a[mt][3],
                      asb + aoff + (mt * 16 * 40 + kk) * 2);
#pragma unroll
            for (int p = 0; p < 2; p++) {
                unsigned t0, t1, t2, t3;
                ldsm4(t0, t1, t2, t3, wsb + boff + (p * 16 * 40 + kk) * 2);
                b[2 * p][0] = t0; b[2 * p][1] = t1;
                b[2 * p + 1][0] = t2; b[2 * p + 1][1] = t3;
            }
#pragma unroll
            for (int mt = 0; mt < 2; mt++)
#pragma unroll
                for (int in = 0; in < 4; in++)
                    mmah(acc[mt][in], a[mt], b[in]);
        }
    }

    const int doRelu = flags & 1;
    const int doHalf = flags & 2;
#pragma unroll
    for (int mt = 0; mt < 2; mt++) {
        int row = bm + wm + mt * 16 + r;
#pragma unroll
        for (int in = 0; in < 4; in++) {
            int col = bn + wn + in * 8 + 2 * cq;
            float2 bv = *(const float2*)(bias + col);
            float v0 = acc[mt][in][0] + bv.x;
            float v1 = acc[mt][in][1] + bv.y;
            float v2 = acc[mt][in][2] + bv.x;
            float v3 = acc[mt][in][3] + bv.y;
            if (doRelu) {
                v0 = fmaxf(v0, 0.f); v1 = fmaxf(v1, 0.f);
                v2 = fmaxf(v2, 0.f); v3 = fmaxf(v3, 0.f);
            }
            if (doHalf) {
                __half* C = (__half*)Cv;
                *(__half2*)(C + (size_t)row * N + col) =
                    __floats2half2_rn(v0, v1);
                *(__half2*)(C + (size_t)(row + 8) * N + col) =
                    __floats2half2_rn(v2, v3);
            } else {
                float* C = (float*)Cv;
                *(float2*)(C + (size_t)row * N + col)       = make_float2(v0, v1);
                *(float2*)(C + (size_t)(row + 8) * N + col) = make_float2(v2, v3);
            }
        }
    }
}

// ---------------- persistent recurrent LSTM layer (fp16, bulk h fetch) ----------------
// R10 structure: per step each khalf warp-group fetches its 4 h-chunks (32 KB) as one
// cp.async group; split-K across warp-groups; Gs smem merge; writeAll gates seq stores.

__device__ __forceinline__ void load_h_group(__half* Ha, const __half* ht_in,
                                             int m0, int khalf, int gtid)
{
#pragma unroll
    for (int i = 0; i < 16; i++) {
        int s   = gtid + i * 128;        // 0..2047
        int cl  = s >> 9;                // local chunk 0..3
        int row = (s >> 3) & 63;
        int c8  = (s & 7) << 3;
        int chunk = khalf * 4 + cl;
        cpasync16(Ha + (size_t)chunk * (64 * 72) + row * 72 + c8,
                  ht_in + (size_t)(m0 + row) * HH + chunk * 64 + c8);
    }
}

__device__ __forceinline__ void load_xs(float* dst, const float* xw,
                                        int t, int m0, int j0, int tid)
{
#pragma unroll
    for (int i = 0; i < 4; i++) {
        int s   = tid + i * 256;
        int row = s >> 4;             // 0..63
        int q   = (s >> 2) & 3;
        int f4  = (s & 3) << 2;
        cpasync16(dst + row * 68 + q * 16 + f4,
                  xw + ((size_t)(m0 + row) * TT + t) * GG + q * HH + j0 + f4);
    }
}

__global__ __launch_bounds__(256, 1)
void k_lstm_persist(const float* __restrict__ xw, const __half* __restrict__ WhhR,
                    const float* __restrict__ bhh, __half* __restrict__ seq_out,
                    int writeAll)
{
    extern __shared__ char smc[];
    __half* Bs = (__half*)smc;                    // [64][520] Whh slice
    __half* Ha = (__half*)(smc + P_HA_OFF);       // [8][64][72] h chunks (all resident)
    float*  Xs = (float*)(smc + P_XS_OFF);        // [2][64][68] xw tiles
    float*  Gs = (float*)(smc + P_GS_OFF);        // [2][64][68] split-K partials

    const int tid   = threadIdx.x, lane = tid & 31, warp = tid >> 5;
    const int j0    = blockIdx.x * 16;
    const int m0    = blockIdx.y * 64;
    const int grp   = blockIdx.y;                 // barrier group (32 CTAs)
    const int khalf = warp >> 2;
    const int gtid  = tid & 127;
    const int wmw   = (warp & 1) * 32;
    const int wnw   = ((warp >> 1) & 1) * 32;
    const int jjt   = tid & 15;
    const int mgt   = tid >> 4;

    const unsigned sbB  = (unsigned)__cvta_generic_to_shared(Bs);
    const unsigned sbHa = (unsigned)__cvta_generic_to_shared(Ha);
    const int arow = lane & 15;
    const int kA   = (lane & 16) ? 8 : 0;
    const int brow = (lane & 7) + ((lane & 16) ? 8 : 0);
    const int kB   = (lane & 8) ? 8 : 0;
    const unsigned aoff = ((wmw + arow) * 72 + kA) * 2;
    const unsigned boff = ((wnw + brow) * 520 + kB) * 2;

    // one-time Bs load: row n = jj*4+q <- WhhR row q*512+j0+jj, full K (512 halves)
    {
#pragma unroll
        for (int i = 0; i < 16; i++) {
            int s  = tid + i * 256;       // 0..4095
            int n  = s >> 6;              // 0..63
            int c8 = (s & 63) << 3;       // 0..504
            int jj = n >> 2, q = n & 3;
            cpasync16(Bs + n * 520 + c8, WhhR + (size_t)(q * HH + j0 + jj) * HH + c8);
        }
        cpcommit();
    }
    float bh[4];
#pragma unroll
    for (int q = 0; q < 4; q++) bh[q] = bhh[q * HH + j0 + jjt];

    float cst[4] = {0.f, 0.f, 0.f, 0.f};

    // prologue: xw(0), H(0); full drain + full sync (covers Bs visibility too)
    load_xs(Xs, xw, 0, m0, j0, tid);           cpcommit();
    load_h_group(Ha, g_ht, m0, khalf, gtid);   cpcommit();
    cpwaitN<0>();
    __syncthreads();

    for (int t = 0; t < TT; t++) {
        // drain xw(t) + H(t); group-local visibility for this khalf's chunks
        cpwaitN<0>();
        bar_grp(khalf);

        float acc[2][4][4];
#pragma unroll
        for (int mt = 0; mt < 2; mt++)
#pragma unroll
            for (int in = 0; in < 4; in++)
#pragma unroll
                for (int q = 0; q < 4; q++) acc[mt][in][q] = 0.f;

#pragma unroll
        for (int cl = 0; cl < 4; cl++) {
            const int chunk = khalf * 4 + cl;
            const unsigned hb = sbHa + (unsigned)(chunk * 64 * 72 * 2);
            const int kg0 = chunk * 64;
#pragma unroll
            for (int kk = 0; kk < 64; kk += 16) {
                unsigned a[2][4];
#pragma unroll
                for (int mt = 0; mt < 2; mt++)
                    ldsm4(a[mt][0], a[mt][1], a[mt][2], a[mt][3],
                          hb + aoff + (mt * 16 * 72 + kk) * 2);
                unsigned b[4][2];
#pragma unroll
                for (int p = 0; p < 2; p++) {
                    unsigned t0, t1, t2, t3;
                    ldsm4(t0, t1, t2, t3,
                          sbB + boff + (p * 16 * 520 + kg0 + kk) * 2);
                    b[2 * p][0] = t0; b[2 * p][1] = t1;
                    b[2 * p + 1][0] = t2; b[2 * p + 1][1] = t3;
                }
#pragma unroll
                for (int mt = 0; mt < 2; mt++)
#pragma unroll
                    for (int in = 0; in < 4; in++)
                        mmah(acc[mt][in], a[mt], b[in]);
            }
        }

        // commit next step's xw tile early (overlaps epilogue + barrier)
        if (t + 1 < TT) { load_xs(Xs + ((t + 1) & 1) * (64 * 68), xw, t + 1, m0, j0, tid); cpcommit(); }

        // write split-K partials (disjoint per khalf)
        {
            const int r = lane >> 2, cq = lane & 3;
            float* G = Gs + khalf * (64 * 68);
#pragma unroll
            for (int mt = 0; mt < 2; mt++) {
                int row = wmw + mt * 16 + r;
#pragma unroll
                for (int in = 0; in < 4; in++) {
                    int col = wnw + in * 8 + 2 * cq;
                    *(float2*)&G[row * 68 + col]       = make_float2(acc[mt][in][0], acc[mt][in][1]);
                    *(float2*)&G[(row + 8) * 68 + col] = make_float2(acc[mt][in][2], acc[mt][in][3]);
                }
            }
        }
        __syncthreads();

        // epilogue: thread (jjt, m = mgt+16*it)
        const int pin = t & 1;
        __half* ht_out = g_ht + (size_t)(pin ^ 1) * (BQ * HH);
        const float* xs  = Xs + (t & 1) * (64 * 68);
        const float* GsA = Gs;
        const float* GsB = Gs + 64 * 68;
        const int doSeq = writeAll | (t == TT - 1);
#pragma unroll
        for (int it = 0; it < 4; it++) {
            int m = mgt + it * 16;
            float4 ga = *(const float4*)&GsA[m * 68 + jjt * 4];
            float4 gb = *(const float4*)&GsB[m * 68 + jjt * 4];
            float gi = ga.x + gb.x + xs[m * 68 +      jjt] + bh[0];
            float gf = ga.y + gb.y + xs[m * 68 + 16 + jjt] + bh[1];
            float gg = ga.z + gb.z + xs[m * 68 + 32 + jjt] + bh[2];
            float go = ga.w + gb.w + xs[m * 68 + 48 + jjt] + bh[3];
            float iv = sigm(gi), fv = sigm(gf);
            float gv = tanhfast(gg), ov = sigm(go);
            float cv = fv * cst[it] + iv * gv;
            cst[it] = cv;
            float hv = ov * tanhfast(cv);
            ht_out[(size_t)(m0 + m) * HH + j0 + jjt] = __float2half_rn(hv);
            if (doSeq)
                seq_out[((size_t)(m0 + m) * TT + t) * HH + j0 + jjt] =
                    __float2half_rn(fmaxf(hv, 0.f));
        }

        // per-m0-group barrier (32 CTAs), last-arriver release, cumulative counts
        __threadfence();
        __syncthreads();
        if (tid == 0) {
            unsigned old = atomicAdd(&g_cnt[grp], 1u);
            if (old == 32u * (unsigned)(t + 1) - 1u) {
                __threadfence();
                *(volatile unsigned*)&g_gen[grp] = (unsigned)(t + 1);
            } else {
                while (*(volatile unsigned*)&g_gen[grp] < (unsigned)(t + 1)) { }
                __threadfence();
            }
        }
        __syncthreads();

        // issue H(t+1) bulk fetch (one group per khalf)
        if (t + 1 < TT) {
            const __half* hin2 = g_ht + (size_t)((t + 1) & 1) * (BQ * HH);
            load_h_group(Ha, hin2, m0, khalf, gtid);
            cpcommit();
        }
    }
}

// ---------------- heads ----------------
__global__ void k_head(const __half* __restrict__ seq,
                       const float* __restrict__ W_out, const float* __restrict__ b_out,
                       const float* __restrict__ W_cls, const float* __restrict__ b_cls,
                       float* __restrict__ out)
{
    int idx = blockIdx.x * blockDim.x + threadIdx.x;
    if (idx >= BQ * 560) return;
    int b = idx / 560, c = idx % 560;
    const __half* last = seq + ((size_t)b * TT + (TT - 1)) * HH;
    if (c < NCONT) {
        float s = b_out[c];
#pragma unroll 4
        for (int k = 0; k < HH; k++) s += __half2float(last[k]) * W_out[k * NCONT + c];
        out[b * NCONT + c] = s;
    } else {
        int cc = c - NCONT;
        int n = cc >> 5, v = cc & 31;
        float s = b_cls[n * VV + v];
        const float* w = W_cls + (size_t)n * HH * VV + v;
#pragma unroll 4
        for (int k = 0; k < HH; k++) s += __half2float(last[k]) * w[k * VV];
        out[BQ * NCONT + (size_t)b * (NCAT * VV) + cc] = s;
    }
}

// ---------------- launch ----------------
extern "C" void kernel_launch(void* const* d_in, const int* in_sizes, int n_in,
                              void* d_out, int out_size)
{
    const float* x      = (const float*)d_in[0];
    const float* smean  = (const float*)d_in[1];
    const float* sscale = (const float*)d_in[2];
    const float* emb    = (const float*)d_in[3];
    const float* W_in   = (const float*)d_in[4];
    const float* b_in   = (const float*)d_in[5];
    const float* Wih    = (const float*)d_in[6];
    const float* Whh    = (const float*)d_in[7];
    const float* bih    = (const float*)d_in[8];
    const float* bhh    = (const float*)d_in[9];
    const float* W_out  = (const float*)d_in[10];
    const float* b_out  = (const float*)d_in[11];
    const float* W_cls  = (const float*)d_in[12];
    const float* b_cls  = (const float*)d_in[13];
    float* out = (float*)d_out;

    __half *feat, *seq0, *seq1, *winT, *wihR, *whhR;
    float *xw;
    cudaGetSymbolAddress((void**)&feat, g_feat);
    cudaGetSymbolAddress((void**)&seq0, g_seq0);
    cudaGetSymbolAddress((void**)&seq1, g_seq1);
    cudaGetSymbolAddress((void**)&xw,   g_xw);
    cudaGetSymbolAddress((void**)&winT, g_WinT);
    cudaGetSymbolAddress((void**)&wihR, g_WihR);
    cudaGetSymbolAddress((void**)&whhR, g_WhhR);

    cudaFuncSetAttribute(k_lstm_persist, cudaFuncAttributeMaxDynamicSharedMemorySize,
                         PERSIST_SMEM);
    cudaFuncSetAttribute(k_gemm_fp16, cudaFuncAttributeMaxDynamicSharedMemorySize,
                         GEMM_SMEM);

    k_transpose_win<<<(HH * INP + 255) / 256, 256>>>(W_in, winT);
    k_round2<<<(2 * GG * HH + 255) / 256, 256>>>(Wih, wihR, Whh, whhR);
    k_build_feat<<<(MT * INP + 255) / 256, 256>>>(x, smean, sscale, emb, feat);

    // input projection: seq0 = half(relu(feat @ W_in + b_in)), K=192
    {
        dim3 grid(HH / 128, MT / 128);
        k_gemm_fp16<<<grid, 512, GEMM_SMEM>>>(feat, winT, b_in, seq0, MT, HH, INP, 3);
    }

    const __half* seq_in  = seq0;
    __half*       seq_out = seq1;
    for (int l = 0; l < 2; l++) {
        const __half* Wih_l = wihR + (size_t)l * GG * HH;
        const __half* Whh_l = whhR + (size_t)l * GG * HH;
        const float*  bih_l = bih  + (size_t)l * GG;
        const float*  bhh_l = bhh  + (size_t)l * GG;

        // xw = seq_in @ Wih^T + bih  (fp32 output)
        {
            dim3 grid(GG / 128, MT / 128);
            k_gemm_fp16<<<grid, 512, GEMM_SMEM>>>(seq_in, Wih_l, bih_l, xw, MT, GG, HH, 0);
        }
        k_reset<<<(BQ * HH + 255) / 256, 256>>>();
        {
            dim3 grid(HH / 16, BQ / 64);   // (32, 4) = 128 CTAs
            k_lstm_persist<<<grid, 256, PERSIST_SMEM>>>(xw, Whh_l, bhh_l, seq_out,
                                                        (l == 0) ? 1 : 0);
        }
        const __half* tmp_in = seq_out;
        seq_out = (__half*)seq_in;
        seq_in  = tmp_in;
    }

    k_head<<<(BQ * 560 + 255) / 256, 256>>>(seq_in, W_out, b_out, W_cls, b_cls, out);
}

// round 14
// speedup vs baseline: 1.0233x; 1.0233x over previous
#include <cuda_runtime.h>
#include <cuda_fp16.h>
#include <math.h>
#include <stdint.h>

// ---------------- problem constants ----------------
#define BQ     256
#define TT     100
#define NFEAT  64
#define VV     32
#define EE     8
#define HH     512
#define NCAT   16
#define NCONT  48
#define INLEN  176
#define INP    192        // padded K for input projection
#define GG     2048
#define MT     (BQ*TT)

// persist smem (bytes): Bs half[64][520] + Ha half[8][64][72] + Xs f32[2][64][68] + Gs f32[2][64][68]
#define P_BS_B   (64*520*2)                 // 66,560
#define P_HA_B   (8*64*72*2)                // 73,728
#define P_XS_B   (2*64*68*4)                // 34,816
#define P_GS_B   (2*64*68*4)                // 34,816
#define P_HA_OFF (P_BS_B)
#define P_XS_OFF (P_BS_B + P_HA_B)
#define P_GS_OFF (P_BS_B + P_HA_B + P_XS_B)
#define PERSIST_SMEM (P_BS_B + P_HA_B + P_XS_B + P_GS_B)   // 209,920 B

// GEMM smem: 4 stages x (A 128x40 + W 128x40) halves
#define ASTG_H   (128*40)
#define ASTG_B   (ASTG_H*2)                 // 10,240 B
#define GEMM_SMEM (4 * 2 * ASTG_B)          // 81,920 B

// ---------------- scratch ----------------
__device__ __half g_feat[MT * INP + 64];
__device__ __half g_seq0[MT * HH + 64];
__device__ __half g_seq1[MT * HH + 64];
__device__ float  g_xw  [(size_t)MT * GG];
__device__ __half g_WinT[HH * INP + 64];
__device__ __half g_WihR[2 * GG * HH];
__device__ __half g_WhhR[2 * GG * HH];
__device__ __half g_ht  [2 * BQ * HH];      // m-major h state, double buffered
__device__ unsigned g_cnt[4];               // per-m0-group barrier counters
__device__ unsigned g_gen[4];

// ---------------- helpers ----------------
__device__ __forceinline__ void mmah(float* d, const unsigned* a, const unsigned* b) {
    asm volatile("mma.sync.aligned.m16n8k16.row.col.f32.f16.f16.f32 "
                 "{%0,%1,%2,%3}, {%4,%5,%6,%7}, {%8,%9}, {%0,%1,%2,%3};"
                 : "+f"(d[0]), "+f"(d[1]), "+f"(d[2]), "+f"(d[3])
                 : "r"(a[0]), "r"(a[1]), "r"(a[2]), "r"(a[3]), "r"(b[0]), "r"(b[1]));
}

__device__ __forceinline__ void ldsm4(unsigned& r0, unsigned& r1, unsigned& r2, unsigned& r3,
                                      unsigned addr) {
    asm volatile("ldmatrix.sync.aligned.m8n8.x4.shared.b16 {%0,%1,%2,%3}, [%4];"
                 : "=r"(r0), "=r"(r1), "=r"(r2), "=r"(r3) : "r"(addr));
}

__device__ __forceinline__ void cpasync16(void* smem_dst, const void* gsrc) {
    unsigned s = (unsigned)__cvta_generic_to_shared(smem_dst);
    asm volatile("cp.async.cg.shared.global [%0], [%1], 16;" :: "r"(s), "l"(gsrc));
}
__device__ __forceinline__ void cpcommit() { asm volatile("cp.async.commit_group;" ::: "memory"); }
template<int N> __device__ __forceinline__ void cpwaitN() {
    asm volatile("cp.async.wait_group %0;" :: "n"(N) : "memory");
}

__device__ __forceinline__ float sigm(float x)     { return 1.f / (1.f + __expf(-x)); }
__device__ __forceinline__ float tanhfast(float x) { return 2.f / (1.f + __expf(-2.f * x)) - 1.f; }

__device__ __forceinline__ void bar_grp(int khalf) {
    if (khalf == 0) asm volatile("bar.sync 1, 128;" ::: "memory");
    else            asm volatile("bar.sync 2, 128;" ::: "memory");
}

// ---------------- small utility kernels ----------------
__global__ void k_transpose_win(const float* __restrict__ Win, __half* __restrict__ WinT)
{
    int idx = blockIdx.x * blockDim.x + threadIdx.x;   // over HH*INP
    if (idx >= HH * INP) return;
    int n = idx / INP, k = idx % INP;
    WinT[idx] = (k < INLEN) ? __float2half_rn(Win[k * HH + n]) : __float2half_rn(0.f);
}

__global__ void k_round2(const float* __restrict__ A, __half* __restrict__ RA,
                         const float* __restrict__ B, __half* __restrict__ RB)
{
    int i = blockIdx.x * blockDim.x + threadIdx.x;
    if (i < 2 * GG * HH) { RA[i] = __float2half_rn(A[i]); RB[i] = __float2half_rn(B[i]); }
}

__global__ void k_reset()
{
    int i = blockIdx.x * blockDim.x + threadIdx.x;
    if (i < BQ * HH) g_ht[i] = __float2half_rn(0.f);   // only buffer 0 is read at t=0
    if (i < 4) { g_cnt[i] = 0; g_gen[i] = 0; }
}

__global__ void k_build_feat(const float* __restrict__ x,
                             const float* __restrict__ mean,
                             const float* __restrict__ scale,
                             const float* __restrict__ emb,
                             __half* __restrict__ feat)
{
    int idx = blockIdx.x * blockDim.x + threadIdx.x;   // over MT*INP
    if (idx >= MT * INP) return;
    int c = idx % INP;
    int m = idx / INP;
    float v = 0.f;
    if (c < INLEN) {
        int blk = c / 11, r = c % 11;
        if (r < 8) {
            int k  = 4 * blk;
            int xi = (int)x[(size_t)m * NFEAT + k];
            v = emb[((size_t)blk * VV + xi) * EE + r];
        } else {
            int k = 4 * blk + (r - 7);
            v = (x[(size_t)m * NFEAT + k] - mean[k]) / scale[k];
        }
    }
    feat[idx] = __float2half_rn(v);
}

// ---------------- fp16 NT GEMM: 128x128 CTA, 8 warps of 32x64, BK=32(half), 4-stage ----
__device__ __forceinline__ void gemm_load_stage(__half* dstA, __half* dstW,
                                                const __half* A, const __half* W,
                                                int bm, int bn, int K, int k0, int tid)
{
#pragma unroll
    for (int i = 0; i < 2; i++) {
        int e   = tid + i * 256;      // 0..511
        int row = e >> 2;             // 0..127
        int q   = (e & 3) << 3;       // 0,8,16,24 halves
        cpasync16(dstA + row * 40 + q, A + (size_t)(bm + row) * K + k0 + q);
    }
#pragma unroll
    for (int i = 0; i < 2; i++) {
        int e   = tid + i * 256;
        int row = e >> 2;
        int q   = (e & 3) << 3;
        cpasync16(dstW + row * 40 + q, W + (size_t)(bn + row) * K + k0 + q);
    }
}

__global__ __launch_bounds__(256, 2)
void k_gemm_fp16(const __half* __restrict__ A, const __half* __restrict__ W,
                 const float* __restrict__ bias, void* __restrict__ Cv,
                 int M, int N, int K, int flags)   // bit0: relu, bit1: half output
{
    extern __shared__ __half smh[];
    __half* As = smh;                       // [4][128*40]
    __half* Ws = smh + 4 * ASTG_H;

    const int tid  = threadIdx.x;
    const int bm   = blockIdx.y * 128;
    const int bn   = blockIdx.x * 128;
    const int lane = tid & 31, warp = tid >> 5;
    const int wm   = (warp & 3) * 32;       // 4 m-warps, tile 32
    const int wn   = (warp >> 2) * 64;      // 2 n-warps, tile 64
    const int r    = lane >> 2, cq = lane & 3;
    const int NK   = K >> 5;                // K % 32 == 0, NK >= 3

    const unsigned sbg = (unsigned)__cvta_generic_to_shared(smh);
    const int arow = lane & 15;
    const int kA   = (lane & 16) ? 8 : 0;   // halves
    const int brow = (lane & 7) + ((lane & 16) ? 8 : 0);
    const int kB   = (lane & 8) ? 8 : 0;    // halves
    const unsigned aoff = ((wm + arow) * 40 + kA) * 2;
    const unsigned boff = ((wn + brow) * 40 + kB) * 2;

    float acc[2][8][4];
#pragma unroll
    for (int mt = 0; mt < 2; mt++)
#pragma unroll
        for (int in = 0; in < 8; in++)
#pragma unroll
            for (int q = 0; q < 4; q++) acc[mt][in][q] = 0.f;

    gemm_load_stage(As, Ws, A, W, bm, bn, K, 0, tid); cpcommit();
    gemm_load_stage(As + ASTG_H, Ws + ASTG_H, A, W, bm, bn, K, 32, tid); cpcommit();
    gemm_load_stage(As + 2 * ASTG_H, Ws + 2 * ASTG_H, A, W, bm, bn, K, 64, tid); cpcommit();

    for (int kc = 0; kc < NK; kc++) {
        if      (kc < NK - 2) cpwaitN<2>();
        else if (kc < NK - 1) cpwaitN<1>();
        else                  cpwaitN<0>();
        __syncthreads();
        if (kc + 3 < NK) {
            int s = (kc + 3) & 3;
            gemm_load_stage(As + s * ASTG_H, Ws + s * ASTG_H, A, W, bm, bn, K,
                            (kc + 3) << 5, tid);
            cpcommit();
        }
        const unsigned asb = sbg + (kc & 3) * ASTG_B;
        const unsigned wsb = sbg + 4 * ASTG_B + (kc & 3) * ASTG_B;
#pragma unroll
        for (int kk = 0; kk < 32; kk += 16) {
            unsigned a[2][4], b[8][2];
#pragma unroll
            for (int mt = 0; mt < 2; mt++)
                ldsm4(a[mt][0], a[mt][1], a[mt][2], a[mt][3],
                      asb + aoff + (mt * 16 * 40 + kk) * 2);
#pragma unroll
            for (int p = 0; p < 4; p++) {
                unsigned t0, t1, t2, t3;
                ldsm4(t0, t1, t2, t3, wsb + boff + (p * 16 * 40 + kk) * 2);
                b[2 * p][0] = t0; b[2 * p][1] = t1;
                b[2 * p + 1][0] = t2; b[2 * p + 1][1] = t3;
            }
#pragma unroll
            for (int mt = 0; mt < 2; mt++)
#pragma unroll
                for (int in = 0; in < 8; in++)
                    mmah(acc[mt][in], a[mt], b[in]);
        }
    }

    const int doRelu = flags & 1;
    const int doHalf = flags & 2;
#pragma unroll
    for (int mt = 0; mt < 2; mt++) {
        int row = bm + wm + mt * 16 + r;
#pragma unroll
        for (int in = 0; in < 8; in++) {
            int col = bn + wn + in * 8 + 2 * cq;
            float2 bv = *(const float2*)(bias + col);
            float v0 = acc[mt][in][0] + bv.x;
            float v1 = acc[mt][in][1] + bv.y;
            float v2 = acc[mt][in][2] + bv.x;
            float v3 = acc[mt][in][3] + bv.y;
            if (doRelu) {
                v0 = fmaxf(v0, 0.f); v1 = fmaxf(v1, 0.f);
                v2 = fmaxf(v2, 0.f); v3 = fmaxf(v3, 0.f);
            }
            if (doHalf) {
                __half* C = (__half*)Cv;
                *(__half2*)(C + (size_t)row * N + col) =
                    __floats2half2_rn(v0, v1);
                *(__half2*)(C + (size_t)(row + 8) * N + col) =
                    __floats2half2_rn(v2, v3);
            } else {
                float* C = (float*)Cv;
                *(float2*)(C + (size_t)row * N + col)       = make_float2(v0, v1);
                *(float2*)(C + (size_t)(row + 8) * N + col) = make_float2(v2, v3);
            }
        }
    }
}

// ---------------- persistent recurrent LSTM layer (fp16, 2-wave h fetch) ----------------
// Per step, per khalf warp-group: h fetched as TWO commit groups (2 chunks each).
// wait<1> drains xw(t)+wave-a -> compute chunks 0-1 while wave-b in flight;
// wait<0> -> compute chunks 2-3. Split-K + Gs merge as in R10/R12.

__device__ __forceinline__ void load_h_wave(__half* Ha, const __half* ht_in,
                                            int m0, int khalf, int wave, int gtid)
{
#pragma unroll
    for (int i = 0; i < 8; i++) {
        int s   = gtid + i * 128;        // 0..1023
        int cl  = s >> 9;                // 0..1
        int row = (s >> 3) & 63;
        int c8  = (s & 7) << 3;
        int chunk = khalf * 4 + wave * 2 + cl;
        cpasync16(Ha + (size_t)chunk * (64 * 72) + row * 72 + c8,
                  ht_in + (size_t)(m0 + row) * HH + chunk * 64 + c8);
    }
}

__device__ __forceinline__ void load_xs(float* dst, const float* xw,
                                        int t, int m0, int j0, int tid)
{
#pragma unroll
    for (int i = 0; i < 4; i++) {
        int s   = tid + i * 256;
        int row = s >> 4;             // 0..63
        int q   = (s >> 2) & 3;
        int f4  = (s & 3) << 2;
        cpasync16(dst + row * 68 + q * 16 + f4,
                  xw + ((size_t)(m0 + row) * TT + t) * GG + q * HH + j0 + f4);
    }
}

__global__ __launch_bounds__(256, 1)
void k_lstm_persist(const float* __restrict__ xw, const __half* __restrict__ WhhR,
                    const float* __restrict__ bhh, __half* __restrict__ seq_out,
                    int writeAll)
{
    extern __shared__ char smc[];
    __half* Bs = (__half*)smc;                    // [64][520] Whh slice
    __half* Ha = (__half*)(smc + P_HA_OFF);       // [8][64][72] h chunks (all resident)
    float*  Xs = (float*)(smc + P_XS_OFF);        // [2][64][68] xw tiles
    float*  Gs = (float*)(smc + P_GS_OFF);        // [2][64][68] split-K partials

    const int tid   = threadIdx.x, lane = tid & 31, warp = tid >> 5;
    const int j0    = blockIdx.x * 16;
    const int m0    = blockIdx.y * 64;
    const int grp   = blockIdx.y;                 // barrier group (32 CTAs)
    const int khalf = warp >> 2;
    const int gtid  = tid & 127;
    const int wmw   = (warp & 1) * 32;
    const int wnw   = ((warp >> 1) & 1) * 32;
    const int jjt   = tid & 15;
    const int mgt   = tid >> 4;

    const unsigned sbB  = (unsigned)__cvta_generic_to_shared(Bs);
    const unsigned sbHa = (unsigned)__cvta_generic_to_shared(Ha);
    const int arow = lane & 15;
    const int kA   = (lane & 16) ? 8 : 0;
    const int brow = (lane & 7) + ((lane & 16) ? 8 : 0);
    const int kB   = (lane & 8) ? 8 : 0;
    const unsigned aoff = ((wmw + arow) * 72 + kA) * 2;
    const unsigned boff = ((wnw + brow) * 520 + kB) * 2;

    // one-time Bs load: row n = jj*4+q <- WhhR row q*512+j0+jj, full K (512 halves)
    {
#pragma unroll
        for (int i = 0; i < 16; i++) {
            int s  = tid + i * 256;       // 0..4095
            int n  = s >> 6;              // 0..63
            int c8 = (s & 63) << 3;       // 0..504
            int jj = n >> 2, q = n & 3;
            cpasync16(Bs + n * 520 + c8, WhhR + (size_t)(q * HH + j0 + jj) * HH + c8);
        }
        cpcommit();
    }
    float bh[4];
#pragma unroll
    for (int q = 0; q < 4; q++) bh[q] = bhh[q * HH + j0 + jjt];

    float cst[4] = {0.f, 0.f, 0.f, 0.f};

    // prologue: drain Bs, then commit xw(0), Ha(0), Hb(0)
    cpwaitN<0>();
    __syncthreads();
    load_xs(Xs, xw, 0, m0, j0, tid);                cpcommit();
    load_h_wave(Ha, g_ht, m0, khalf, 0, gtid);      cpcommit();
    load_h_wave(Ha, g_ht, m0, khalf, 1, gtid);      cpcommit();

    for (int t = 0; t < TT; t++) {
        // pending (oldest first): xw(t), Ha(t), Hb(t)
        cpwaitN<1>();              // drains xw(t) + Ha(t)
        bar_grp(khalf);

        float acc[2][4][4];
#pragma unroll
        for (int mt = 0; mt < 2; mt++)
#pragma unroll
            for (int in = 0; in < 4; in++)
#pragma unroll
                for (int q = 0; q < 4; q++) acc[mt][in][q] = 0.f;

#pragma unroll
        for (int cl = 0; cl < 4; cl++) {
            if (cl == 2) {          // wave-b boundary
                cpwaitN<0>();
                bar_grp(khalf);
            }
            const int chunk = khalf * 4 + cl;
            const unsigned hb = sbHa + (unsigned)(chunk * 64 * 72 * 2);
            const int kg0 = chunk * 64;
#pragma unroll
            for (int kk = 0; kk < 64; kk += 16) {
                unsigned a[2][4];
#pragma unroll
                for (int mt = 0; mt < 2; mt++)
                    ldsm4(a[mt][0], a[mt][1], a[mt][2], a[mt][3],
                          hb + aoff + (mt * 16 * 72 + kk) * 2);
                unsigned b[4][2];
#pragma unroll
                for (int p = 0; p < 2; p++) {
                    unsigned t0, t1, t2, t3;
                    ldsm4(t0, t1, t2, t3,
                          sbB + boff + (p * 16 * 520 + kg0 + kk) * 2);
                    b[2 * p][0] = t0; b[2 * p][1] = t1;
                    b[2 * p + 1][0] = t2; b[2 * p + 1][1] = t3;
                }
#pragma unroll
                for (int mt = 0; mt < 2; mt++)
#pragma unroll
                    for (int in = 0; in < 4; in++)
                        mmah(acc[mt][in], a[mt], b[in]);
            }
        }

        // commit next step's xw tile early (overlaps epilogue + barrier)
        if (t + 1 < TT) { load_xs(Xs + ((t + 1) & 1) * (64 * 68), xw, t + 1, m0, j0, tid); cpcommit(); }

        // write split-K partials (disjoint per khalf)
        {
            const int r = lane >> 2, cq = lane & 3;
            float* G = Gs + khalf * (64 * 68);
#pragma unroll
            for (int mt = 0; mt < 2; mt++) {
                int row = wmw + mt * 16 + r;
#pragma unroll
                for (int in = 0; in < 4; in++) {
                    int col = wnw + in * 8 + 2 * cq;
                    *(float2*)&G[row * 68 + col]       = make_float2(acc[mt][in][0], acc[mt][in][1]);
                    *(float2*)&G[(row + 8) * 68 + col] = make_float2(acc[mt][in][2], acc[mt][in][3]);
                }
            }
        }
        __syncthreads();

        // epilogue: thread (jjt, m = mgt+16*it)
        const int pin = t & 1;
        __half* ht_out = g_ht + (size_t)(pin ^ 1) * (BQ * HH);
        const float* xs  = Xs + (t & 1) * (64 * 68);
        const float* GsA = Gs;
        const float* GsB = Gs + 64 * 68;
        const int doSeq = writeAll | (t == TT - 1);
#pragma unroll
        for (int it = 0; it < 4; it++) {
            int m = mgt + it * 16;
            float4 ga = *(const float4*)&GsA[m * 68 + jjt * 4];
            float4 gb = *(const float4*)&GsB[m * 68 + jjt * 4];
            float gi = ga.x + gb.x + xs[m * 68 +      jjt] + bh[0];
            float gf = ga.y + gb.y + xs[m * 68 + 16 + jjt] + bh[1];
            float gg = ga.z + gb.z + xs[m * 68 + 32 + jjt] + bh[2];
            float go = ga.w + gb.w + xs[m * 68 + 48 + jjt] + bh[3];
            float iv = sigm(gi), fv = sigm(gf);
            float gv = tanhfast(gg), ov = sigm(go);
            float cv = fv * cst[it] + iv * gv;
            cst[it] = cv;
            float hv = ov * tanhfast(cv);
            ht_out[(size_t)(m0 + m) * HH + j0 + jjt] = __float2half_rn(hv);
            if (doSeq)
                seq_out[((size_t)(m0 + m) * TT + t) * HH + j0 + jjt] =
                    __float2half_rn(fmaxf(hv, 0.f));
        }

        // per-m0-group barrier (32 CTAs), last-arriver release, cumulative counts
        __threadfence();
        __syncthreads();
        if (tid == 0) {
            unsigned old = atomicAdd(&g_cnt[grp], 1u);
            if (old == 32u * (unsigned)(t + 1) - 1u) {
                __threadfence();
                *(volatile unsigned*)&g_gen[grp] = (unsigned)(t + 1);
            } else {
                while (*(volatile unsigned*)&g_gen[grp] < (unsigned)(t + 1)) { }
                __threadfence();
            }
        }
        __syncthreads();

        // issue H(t+1) waves (two commit groups per khalf)
        if (t + 1 < TT) {
            const __half* hin2 = g_ht + (size_t)((t + 1) & 1) * (BQ * HH);
            load_h_wave(Ha, hin2, m0, khalf, 0, gtid); cpcommit();
            load_h_wave(Ha, hin2, m0, khalf, 1, gtid); cpcommit();
        }
    }
}

// ---------------- heads ----------------
__global__ void k_head(const __half* __restrict__ seq,
                       const float* __restrict__ W_out, const float* __restrict__ b_out,
                       const float* __restrict__ W_cls, const float* __restrict__ b_cls,
                       float* __restrict__ out)
{
    int idx = blockIdx.x * blockDim.x + threadIdx.x;
    if (idx >= BQ * 560) return;
    int b = idx / 560, c = idx % 560;
    const __half* last = seq + ((size_t)b * TT + (TT - 1)) * HH;
    if (c < NCONT) {
        float s = b_out[c];
#pragma unroll 4
        for (int k = 0; k < HH; k++) s += __half2float(last[k]) * W_out[k * NCONT + c];
        out[b * NCONT + c] = s;
    } else {
        int cc = c - NCONT;
        int n = cc >> 5, v = cc & 31;
        float s = b_cls[n * VV + v];
        const float* w = W_cls + (size_t)n * HH * VV + v;
#pragma unroll 4
        for (int k = 0; k < HH; k++) s += __half2float(last[k]) * w[k * VV];
        out[BQ * NCONT + (size_t)b * (NCAT * VV) + cc] = s;
    }
}

// ---------------- launch ----------------
extern "C" void kernel_launch(void* const* d_in, const int* in_sizes, int n_in,
                              void* d_out, int out_size)
{
    const float* x      = (const float*)d_in[0];
    const float* smean  = (const float*)d_in[1];
    const float* sscale = (const float*)d_in[2];
    const float* emb    = (const float*)d_in[3];
    const float* W_in   = (const float*)d_in[4];
    const float* b_in   = (const float*)d_in[5];
    const float* Wih    = (const float*)d_in[6];
    const float* Whh    = (const float*)d_in[7];
    const float* bih    = (const float*)d_in[8];
    const float* bhh    = (const float*)d_in[9];
    const float* W_out  = (const float*)d_in[10];
    const float* b_out  = (const float*)d_in[11];
    const float* W_cls  = (const float*)d_in[12];
    const float* b_cls  = (const float*)d_in[13];
    float* out = (float*)d_out;

    __half *feat, *seq0, *seq1, *winT, *wihR, *whhR;
    float *xw;
    cudaGetSymbolAddress((void**)&feat, g_feat);
    cudaGetSymbolAddress((void**)&seq0, g_seq0);
    cudaGetSymbolAddress((void**)&seq1, g_seq1);
    cudaGetSymbolAddress((void**)&xw,   g_xw);
    cudaGetSymbolAddress((void**)&winT, g_WinT);
    cudaGetSymbolAddress((void**)&wihR, g_WihR);
    cudaGetSymbolAddress((void**)&whhR, g_WhhR);

    cudaFuncSetAttribute(k_lstm_persist, cudaFuncAttributeMaxDynamicSharedMemorySize,
                         PERSIST_SMEM);
    cudaFuncSetAttribute(k_gemm_fp16, cudaFuncAttributeMaxDynamicSharedMemorySize,
                         GEMM_SMEM);

    k_transpose_win<<<(HH * INP + 255) / 256, 256>>>(W_in, winT);
    k_round2<<<(2 * GG * HH + 255) / 256, 256>>>(Wih, wihR, Whh, whhR);
    k_build_feat<<<(MT * INP + 255) / 256, 256>>>(x, smean, sscale, emb, feat);

    // input projection: seq0 = half(relu(feat @ W_in + b_in)), K=192
    {
        dim3 grid(HH / 128, MT / 128);
        k_gemm_fp16<<<grid, 256, GEMM_SMEM>>>(feat, winT, b_in, seq0, MT, HH, INP, 3);
    }

    const __half* seq_in  = seq0;
    __half*       seq_out = seq1;
    for (int l = 0; l < 2; l++) {
        const __half* Wih_l = wihR + (size_t)l * GG * HH;
        const __half* Whh_l = whhR + (size_t)l * GG * HH;
        const float*  bih_l = bih  + (size_t)l * GG;
        const float*  bhh_l = bhh  + (size_t)l * GG;

        // xw = seq_in @ Wih^T + bih  (fp32 output)
        {
            dim3 grid(GG / 128, MT / 128);
            k_gemm_fp16<<<grid, 256, GEMM_SMEM>>>(seq_in, Wih_l, bih_l, xw, MT, GG, HH, 0);
        }
        k_reset<<<(BQ * HH + 255) / 256, 256>>>();
        {
            dim3 grid(HH / 16, BQ / 64);   // (32, 4) = 128 CTAs
            k_lstm_persist<<<grid, 256, PERSIST_SMEM>>>(xw, Whh_l, bhh_l, seq_out,
                                                        (l == 0) ? 1 : 0);
        }
        const __half* tmp_in = seq_out;
        seq_out = (__half*)seq_in;
        seq_in  = tmp_in;
    }

    k_head<<<(BQ * 560 + 255) / 256, 256>>>(seq_in, W_out, b_out, W_cls, b_cls, out);
}

// round 15
// speedup vs baseline: 1.0314x; 1.0079x over previous
#include <cuda_runtime.h>
#include <cuda_fp16.h>
#include <math.h>
#include <stdint.h>

// ---------------- problem constants ----------------
#define BQ     256
#define TT     100
#define NFEAT  64
#define VV     32
#define EE     8
#define HH     512
#define NCAT   16
#define NCONT  48
#define INLEN  176
#define INP    192        // padded K for input projection
#define GG     2048
#define MT     (BQ*TT)

// persist smem (bytes): Bs half[64][520] + Ha half[8][64][72] + Xs f32[2][64][68] + Gs f32[2][64][68]
#define P_BS_B   (64*520*2)                 // 66,560
#define P_HA_B   (8*64*72*2)                // 73,728
#define P_XS_B   (2*64*68*4)                // 34,816
#define P_GS_B   (2*64*68*4)                // 34,816
#define P_HA_OFF (P_BS_B)
#define P_XS_OFF (P_BS_B + P_HA_B)
#define P_GS_OFF (P_BS_B + P_HA_B + P_XS_B)
#define PERSIST_SMEM (P_BS_B + P_HA_B + P_XS_B + P_GS_B)   // 209,920 B

// GEMM smem: 4 stages x (A 128x40 + W 128x40) halves
#define ASTG_H   (128*40)
#define ASTG_B   (ASTG_H*2)                 // 10,240 B
#define GEMM_SMEM (4 * 2 * ASTG_B)          // 81,920 B

// ---------------- scratch ----------------
__device__ __half g_feat[MT * INP + 64];
__device__ __half g_seq0[MT * HH + 64];
__device__ __half g_seq1[MT * HH + 64];
__device__ float  g_xw  [(size_t)MT * GG];
__device__ __half g_WinT[HH * INP + 64];
__device__ __half g_WihR[2 * GG * HH];
__device__ __half g_WhhR[2 * GG * HH];
__device__ __half g_ht  [2 * BQ * HH];      // m-major h state, double buffered
__device__ unsigned g_cnt[4];               // per-m0-group barrier counters
__device__ unsigned g_gen[4];

// ---------------- helpers ----------------
__device__ __forceinline__ void mmah(float* d, const unsigned* a, const unsigned* b) {
    asm volatile("mma.sync.aligned.m16n8k16.row.col.f32.f16.f16.f32 "
                 "{%0,%1,%2,%3}, {%4,%5,%6,%7}, {%8,%9}, {%0,%1,%2,%3};"
                 : "+f"(d[0]), "+f"(d[1]), "+f"(d[2]), "+f"(d[3])
                 : "r"(a[0]), "r"(a[1]), "r"(a[2]), "r"(a[3]), "r"(b[0]), "r"(b[1]));
}

__device__ __forceinline__ void ldsm4(unsigned& r0, unsigned& r1, unsigned& r2, unsigned& r3,
                                      unsigned addr) {
    asm volatile("ldmatrix.sync.aligned.m8n8.x4.shared.b16 {%0,%1,%2,%3}, [%4];"
                 : "=r"(r0), "=r"(r1), "=r"(r2), "=r"(r3) : "r"(addr));
}

__device__ __forceinline__ void cpasync16(void* smem_dst, const void* gsrc) {
    unsigned s = (unsigned)__cvta_generic_to_shared(smem_dst);
    asm volatile("cp.async.cg.shared.global [%0], [%1], 16;" :: "r"(s), "l"(gsrc));
}
__device__ __forceinline__ void cpcommit() { asm volatile("cp.async.commit_group;" ::: "memory"); }
template<int N> __device__ __forceinline__ void cpwaitN() {
    asm volatile("cp.async.wait_group %0;" :: "n"(N) : "memory");
}

__device__ __forceinline__ float sigm(float x)     { return 1.f / (1.f + __expf(-x)); }
__device__ __forceinline__ float tanhfast(float x) { return 2.f / (1.f + __expf(-2.f * x)) - 1.f; }

__device__ __forceinline__ void bar_grp(int khalf) {
    if (khalf == 0) asm volatile("bar.sync 1, 128;" ::: "memory");
    else            asm volatile("bar.sync 2, 128;" ::: "memory");
}

// ---------------- small utility kernels ----------------
__global__ void k_transpose_win(const float* __restrict__ Win, __half* __restrict__ WinT)
{
    int idx = blockIdx.x * blockDim.x + threadIdx.x;   // over HH*INP
    if (idx >= HH * INP) return;
    int n = idx / INP, k = idx % INP;
    WinT[idx] = (k < INLEN) ? __float2half_rn(Win[k * HH + n]) : __float2half_rn(0.f);
}

__global__ void k_round2(const float* __restrict__ A, __half* __restrict__ RA,
                         const float* __restrict__ B, __half* __restrict__ RB)
{
    int i = blockIdx.x * blockDim.x + threadIdx.x;
    if (i < 2 * GG * HH) { RA[i] = __float2half_rn(A[i]); RB[i] = __float2half_rn(B[i]); }
}

__global__ void k_reset()
{
    int i = blockIdx.x * blockDim.x + threadIdx.x;
    if (i < BQ * HH) g_ht[i] = __float2half_rn(0.f);   // only buffer 0 is read at t=0
    if (i < 4) { g_cnt[i] = 0; g_gen[i] = 0; }
}

__global__ void k_build_feat(const float* __restrict__ x,
                             const float* __restrict__ mean,
                             const float* __restrict__ scale,
                             const float* __restrict__ emb,
                             __half* __restrict__ feat)
{
    int idx = blockIdx.x * blockDim.x + threadIdx.x;   // over MT*INP
    if (idx >= MT * INP) return;
    int c = idx % INP;
    int m = idx / INP;
    float v = 0.f;
    if (c < INLEN) {
        int blk = c / 11, r = c % 11;
        if (r < 8) {
            int k  = 4 * blk;
            int xi = (int)x[(size_t)m * NFEAT + k];
            v = emb[((size_t)blk * VV + xi) * EE + r];
        } else {
            int k = 4 * blk + (r - 7);
            v = (x[(size_t)m * NFEAT + k] - mean[k]) / scale[k];
        }
    }
    feat[idx] = __float2half_rn(v);
}

// ---------------- fp16 NT GEMM: 128x128 CTA, 8 warps of 32x64, BK=32(half), 4-stage ----
__device__ __forceinline__ void gemm_load_stage(__half* dstA, __half* dstW,
                                                const __half* A, const __half* W,
                                                int bm, int bn, int K, int k0, int tid)
{
#pragma unroll
    for (int i = 0; i < 2; i++) {
        int e   = tid + i * 256;      // 0..511
        int row = e >> 2;             // 0..127
        int q   = (e & 3) << 3;       // 0,8,16,24 halves
        cpasync16(dstA + row * 40 + q, A + (size_t)(bm + row) * K + k0 + q);
    }
#pragma unroll
    for (int i = 0; i < 2; i++) {
        int e   = tid + i * 256;
        int row = e >> 2;
        int q   = (e & 3) << 3;
        cpasync16(dstW + row * 40 + q, W + (size_t)(bn + row) * K + k0 + q);
    }
}

__global__ __launch_bounds__(256, 2)
void k_gemm_fp16(const __half* __restrict__ A, const __half* __restrict__ W,
                 const float* __restrict__ bias, void* __restrict__ Cv,
                 int M, int N, int K, int flags)   // bit0: relu, bit1: half output
{
    extern __shared__ __half smh[];
    __half* As = smh;                       // [4][128*40]
    __half* Ws = smh + 4 * ASTG_H;

    const int tid  = threadIdx.x;
    const int bm   = blockIdx.y * 128;
    const int bn   = blockIdx.x * 128;
    const int lane = tid & 31, warp = tid >> 5;
    const int wm   = (warp & 3) * 32;       // 4 m-warps, tile 32
    const int wn   = (warp >> 2) * 64;      // 2 n-warps, tile 64
    const int r    = lane >> 2, cq = lane & 3;
    const int NK   = K >> 5;                // K % 32 == 0, NK >= 3

    const unsigned sbg = (unsigned)__cvta_generic_to_shared(smh);
    const int arow = lane & 15;
    const int kA   = (lane & 16) ? 8 : 0;   // halves
    const int brow = (lane & 7) + ((lane & 16) ? 8 : 0);
    const int kB   = (lane & 8) ? 8 : 0;    // halves
    const unsigned aoff = ((wm + arow) * 40 + kA) * 2;
    const unsigned boff = ((wn + brow) * 40 + kB) * 2;

    float acc[2][8][4];
#pragma unroll
    for (int mt = 0; mt < 2; mt++)
#pragma unroll
        for (int in = 0; in < 8; in++)
#pragma unroll
            for (int q = 0; q < 4; q++) acc[mt][in][q] = 0.f;

    gemm_load_stage(As, Ws, A, W, bm, bn, K, 0, tid); cpcommit();
    gemm_load_stage(As + ASTG_H, Ws + ASTG_H, A, W, bm, bn, K, 32, tid); cpcommit();
    gemm_load_stage(As + 2 * ASTG_H, Ws + 2 * ASTG_H, A, W, bm, bn, K, 64, tid); cpcommit();

    for (int kc = 0; kc < NK; kc++) {
        if      (kc < NK - 2) cpwaitN<2>();
        else if (kc < NK - 1) cpwaitN<1>();
        else                  cpwaitN<0>();
        __syncthreads();
        if (kc + 3 < NK) {
            int s = (kc + 3) & 3;
            gemm_load_stage(As + s * ASTG_H, Ws + s * ASTG_H, A, W, bm, bn, K,
                            (kc + 3) << 5, tid);
            cpcommit();
        }
        const unsigned asb = sbg + (kc & 3) * ASTG_B;
        const unsigned wsb = sbg + 4 * ASTG_B + (kc & 3) * ASTG_B;
#pragma unroll
        for (int kk = 0; kk < 32; kk += 16) {
            unsigned a[2][4], b[8][2];
#pragma unroll
            for (int mt = 0; mt < 2; mt++)
                ldsm4(a[mt][0], a[mt][1], a[mt][2], a[mt][3],
                      asb + aoff + (mt * 16 * 40 + kk) * 2);
#pragma unroll
            for (int p = 0; p < 4; p++) {
                unsigned t0, t1, t2, t3;
                ldsm4(t0, t1, t2, t3, wsb + boff + (p * 16 * 40 + kk) * 2);
                b[2 * p][0] = t0; b[2 * p][1] = t1;
                b[2 * p + 1][0] = t2; b[2 * p + 1][1] = t3;
            }
#pragma unroll
            for (int mt = 0; mt < 2; mt++)
#pragma unroll
                for (int in = 0; in < 8; in++)
                    mmah(acc[mt][in], a[mt], b[in]);
        }
    }

    const int doRelu = flags & 1;
    const int doHalf = flags & 2;
#pragma unroll
    for (int mt = 0; mt < 2; mt++) {
        int row = bm + wm + mt * 16 + r;
#pragma unroll
        for (int in = 0; in < 8; in++) {
            int col = bn + wn + in * 8 + 2 * cq;
            float2 bv = *(const float2*)(bias + col);
            float v0 = acc[mt][in][0] + bv.x;
            float v1 = acc[mt][in][1] + bv.y;
            float v2 = acc[mt][in][2] + bv.x;
            float v3 = acc[mt][in][3] + bv.y;
            if (doRelu) {
                v0 = fmaxf(v0, 0.f); v1 = fmaxf(v1, 0.f);
                v2 = fmaxf(v2, 0.f); v3 = fmaxf(v3, 0.f);
            }
            if (doHalf) {
                __half* C = (__half*)Cv;
                *(__half2*)(C + (size_t)row * N + col) =
                    __floats2half2_rn(v0, v1);
                *(__half2*)(C + (size_t)(row + 8) * N + col) =
                    __floats2half2_rn(v2, v3);
            } else {
                float* C = (float*)Cv;
                *(float2*)(C + (size_t)row * N + col)       = make_float2(v0, v1);
                *(float2*)(C + (size_t)(row + 8) * N + col) = make_float2(v2, v3);
            }
        }
    }
}

// ---------------- persistent recurrent LSTM layer (fp16, 4-wave h fetch) ----------------
// Per step, per khalf warp-group: h fetched as FOUR commit groups (1 chunk each).
// Wait ladder <3>/<2>/<1>/<0> before chunks 0..3. seq stores deferred to after
// barrier arrival (only ht_out is cross-CTA data).

__device__ __forceinline__ void load_h_wave(__half* Ha, const __half* ht_in,
                                            int m0, int khalf, int wave, int gtid)
{
#pragma unroll
    for (int i = 0; i < 4; i++) {
        int s   = gtid + i * 128;        // 0..511
        int row = s >> 3;                // 0..63
        int c8  = (s & 7) << 3;
        int chunk = khalf * 4 + wave;
        cpasync16(Ha + (size_t)chunk * (64 * 72) + row * 72 + c8,
                  ht_in + (size_t)(m0 + row) * HH + chunk * 64 + c8);
    }
}

__device__ __forceinline__ void load_xs(float* dst, const float* xw,
                                        int t, int m0, int j0, int tid)
{
#pragma unroll
    for (int i = 0; i < 4; i++) {
        int s   = tid + i * 256;
        int row = s >> 4;             // 0..63
        int q   = (s >> 2) & 3;
        int f4  = (s & 3) << 2;
        cpasync16(dst + row * 68 + q * 16 + f4,
                  xw + ((size_t)(m0 + row) * TT + t) * GG + q * HH + j0 + f4);
    }
}

__global__ __launch_bounds__(256, 1)
void k_lstm_persist(const float* __restrict__ xw, const __half* __restrict__ WhhR,
                    const float* __restrict__ bhh, __half* __restrict__ seq_out,
                    int writeAll)
{
    extern __shared__ char smc[];
    __half* Bs = (__half*)smc;                    // [64][520] Whh slice
    __half* Ha = (__half*)(smc + P_HA_OFF);       // [8][64][72] h chunks (all resident)
    float*  Xs = (float*)(smc + P_XS_OFF);        // [2][64][68] xw tiles
    float*  Gs = (float*)(smc + P_GS_OFF);        // [2][64][68] split-K partials

    const int tid   = threadIdx.x, lane = tid & 31, warp = tid >> 5;
    const int j0    = blockIdx.x * 16;
    const int m0    = blockIdx.y * 64;
    const int grp   = blockIdx.y;                 // barrier group (32 CTAs)
    const int khalf = warp >> 2;
    const int gtid  = tid & 127;
    const int wmw   = (warp & 1) * 32;
    const int wnw   = ((warp >> 1) & 1) * 32;
    const int jjt   = tid & 15;
    const int mgt   = tid >> 4;

    const unsigned sbB  = (unsigned)__cvta_generic_to_shared(Bs);
    const unsigned sbHa = (unsigned)__cvta_generic_to_shared(Ha);
    const int arow = lane & 15;
    const int kA   = (lane & 16) ? 8 : 0;
    const int brow = (lane & 7) + ((lane & 16) ? 8 : 0);
    const int kB   = (lane & 8) ? 8 : 0;
    const unsigned aoff = ((wmw + arow) * 72 + kA) * 2;
    const unsigned boff = ((wnw + brow) * 520 + kB) * 2;

    // one-time Bs load: row n = jj*4+q <- WhhR row q*512+j0+jj, full K (512 halves)
    {
#pragma unroll
        for (int i = 0; i < 16; i++) {
            int s  = tid + i * 256;       // 0..4095
            int n  = s >> 6;              // 0..63
            int c8 = (s & 63) << 3;       // 0..504
            int jj = n >> 2, q = n & 3;
            cpasync16(Bs + n * 520 + c8, WhhR + (size_t)(q * HH + j0 + jj) * HH + c8);
        }
        cpcommit();
    }
    float bh[4];
#pragma unroll
    for (int q = 0; q < 4; q++) bh[q] = bhh[q * HH + j0 + jjt];

    float cst[4] = {0.f, 0.f, 0.f, 0.f};

    // prologue: drain Bs, then commit xw(0), 4 h-waves
    cpwaitN<0>();
    __syncthreads();
    load_xs(Xs, xw, 0, m0, j0, tid);                cpcommit();
#pragma unroll
    for (int w = 0; w < 4; w++) { load_h_wave(Ha, g_ht, m0, khalf, w, gtid); cpcommit(); }

    for (int t = 0; t < TT; t++) {
        float acc[2][4][4];
#pragma unroll
        for (int mt = 0; mt < 2; mt++)
#pragma unroll
            for (int in = 0; in < 4; in++)
#pragma unroll
                for (int q = 0; q < 4; q++) acc[mt][in][q] = 0.f;

        // pending (oldest first): xw(t), w0, w1, w2, w3
#pragma unroll
        for (int cl = 0; cl < 4; cl++) {
            if      (cl == 0) cpwaitN<3>();   // drains xw(t) + w0
            else if (cl == 1) cpwaitN<2>();
            else if (cl == 2) cpwaitN<1>();
            else              cpwaitN<0>();
            bar_grp(khalf);
            const int chunk = khalf * 4 + cl;
            const unsigned hb = sbHa + (unsigned)(chunk * 64 * 72 * 2);
            const int kg0 = chunk * 64;
#pragma unroll
            for (int kk = 0; kk < 64; kk += 16) {
                unsigned a[2][4];
#pragma unroll
                for (int mt = 0; mt < 2; mt++)
                    ldsm4(a[mt][0], a[mt][1], a[mt][2], a[mt][3],
                          hb + aoff + (mt * 16 * 72 + kk) * 2);
                unsigned b[4][2];
#pragma unroll
                for (int p = 0; p < 2; p++) {
                    unsigned t0, t1, t2, t3;
                    ldsm4(t0, t1, t2, t3,
                          sbB + boff + (p * 16 * 520 + kg0 + kk) * 2);
                    b[2 * p][0] = t0; b[2 * p][1] = t1;
                    b[2 * p + 1][0] = t2; b[2 * p + 1][1] = t3;
                }
#pragma unroll
                for (int mt = 0; mt < 2; mt++)
#pragma unroll
                    for (int in = 0; in < 4; in++)
                        mmah(acc[mt][in], a[mt], b[in]);
            }
        }

        // commit next step's xw tile early (overlaps merge + epilogue + barrier)
        if (t + 1 < TT) { load_xs(Xs + ((t + 1) & 1) * (64 * 68), xw, t + 1, m0, j0, tid); cpcommit(); }

        // write split-K partials (disjoint per khalf)
        {
            const int r = lane >> 2, cq = lane & 3;
            float* G = Gs + khalf * (64 * 68);
#pragma unroll
            for (int mt = 0; mt < 2; mt++) {
                int row = wmw + mt * 16 + r;
#pragma unroll
                for (int in = 0; in < 4; in++) {
                    int col = wnw + in * 8 + 2 * cq;
                    *(float2*)&G[row * 68 + col]       = make_float2(acc[mt][in][0], acc[mt][in][1]);
                    *(float2*)&G[(row + 8) * 68 + col] = make_float2(acc[mt][in][2], acc[mt][in][3]);
                }
            }
        }
        __syncthreads();

        // epilogue: thread (jjt, m = mgt+16*it); keep hv in regs, store only ht_out now
        const int pin = t & 1;
        __half* ht_out = g_ht + (size_t)(pin ^ 1) * (BQ * HH);
        const float* xs  = Xs + (t & 1) * (64 * 68);
        const float* GsA = Gs;
        const float* GsB = Gs + 64 * 68;
        float hvreg[4];
#pragma unroll
        for (int it = 0; it < 4; it++) {
            int m = mgt + it * 16;
            float4 ga = *(const float4*)&GsA[m * 68 + jjt * 4];
            float4 gb = *(const float4*)&GsB[m * 68 + jjt * 4];
            float gi = ga.x + gb.x + xs[m * 68 +      jjt] + bh[0];
            float gf = ga.y + gb.y + xs[m * 68 + 16 + jjt] + bh[1];
            float gg = ga.z + gb.z + xs[m * 68 + 32 + jjt] + bh[2];
            float go = ga.w + gb.w + xs[m * 68 + 48 + jjt] + bh[3];
            float iv = sigm(gi), fv = sigm(gf);
            float gv = tanhfast(gg), ov = sigm(go);
            float cv = fv * cst[it] + iv * gv;
            cst[it] = cv;
            float hv = ov * tanhfast(cv);
            hvreg[it] = hv;
            ht_out[(size_t)(m0 + m) * HH + j0 + jjt] = __float2half_rn(hv);
        }

        // per-m0-group barrier (32 CTAs), last-arriver release, cumulative counts
        __threadfence();
        __syncthreads();
        if (tid == 0) {
            unsigned old = atomicAdd(&g_cnt[grp], 1u);
            if (old == 32u * (unsigned)(t + 1) - 1u) {
                __threadfence();
                *(volatile unsigned*)&g_gen[grp] = (unsigned)(t + 1);
            } else {
                while (*(volatile unsigned*)&g_gen[grp] < (unsigned)(t + 1)) { }
                __threadfence();
            }
        }
        __syncthreads();

        // issue H(t+1) waves first, then deferred seq stores (off critical path)
        if (t + 1 < TT) {
            const __half* hin2 = g_ht + (size_t)((t + 1) & 1) * (BQ * HH);
#pragma unroll
            for (int w = 0; w < 4; w++) { load_h_wave(Ha, hin2, m0, khalf, w, gtid); cpcommit(); }
        }
        if (writeAll | (t == TT - 1)) {
#pragma unroll
            for (int it = 0; it < 4; it++) {
                int m = mgt + it * 16;
                seq_out[((size_t)(m0 + m) * TT + t) * HH + j0 + jjt] =
                    __float2half_rn(fmaxf(hvreg[it], 0.f));
            }
        }
    }
}

// ---------------- heads ----------------
__global__ void k_head(const __half* __restrict__ seq,
                       const float* __restrict__ W_out, const float* __restrict__ b_out,
                       const float* __restrict__ W_cls, const float* __restrict__ b_cls,
                       float* __restrict__ out)
{
    int idx = blockIdx.x * blockDim.x + threadIdx.x;
    if (idx >= BQ * 560) return;
    int b = idx / 560, c = idx % 560;
    const __half* last = seq + ((size_t)b * TT + (TT - 1)) * HH;
    if (c < NCONT) {
        float s = b_out[c];
#pragma unroll 4
        for (int k = 0; k < HH; k++) s += __half2float(last[k]) * W_out[k * NCONT + c];
        out[b * NCONT + c] = s;
    } else {
        int cc = c - NCONT;
        int n = cc >> 5, v = cc & 31;
        float s = b_cls[n * VV + v];
        const float* w = W_cls + (size_t)n * HH * VV + v;
#pragma unroll 4
        for (int k = 0; k < HH; k++) s += __half2float(last[k]) * w[k * VV];
        out[BQ * NCONT + (size_t)b * (NCAT * VV) + cc] = s;
    }
}

// ---------------- launch ----------------
extern "C" void kernel_launch(void* const* d_in, const int* in_sizes, int n_in,
                              void* d_out, int out_size)
{
    const float* x      = (const float*)d_in[0];
    const float* smean  = (const float*)d_in[1];
    const float* sscale = (const float*)d_in[2];
    const float* emb    = (const float*)d_in[3];
    const float* W_in   = (const float*)d_in[4];
    const float* b_in   = (const float*)d_in[5];
    const float* Wih    = (const float*)d_in[6];
    const float* Whh    = (const float*)d_in[7];
    const float* bih    = (const float*)d_in[8];
    const float* bhh    = (const float*)d_in[9];
    const float* W_out  = (const float*)d_in[10];
    const float* b_out  = (const float*)d_in[11];
    const float* W_cls  = (const float*)d_in[12];
    const float* b_cls  = (const float*)d_in[13];
    float* out = (float*)d_out;

    __half *feat, *seq0, *seq1, *winT, *wihR, *whhR;
    float *xw;
    cudaGetSymbolAddress((void**)&feat, g_feat);
    cudaGetSymbolAddress((void**)&seq0, g_seq0);
    cudaGetSymbolAddress((void**)&seq1, g_seq1);
    cudaGetSymbolAddress((void**)&xw,   g_xw);
    cudaGetSymbolAddress((void**)&winT, g_WinT);
    cudaGetSymbolAddress((void**)&wihR, g_WihR);
    cudaGetSymbolAddress((void**)&whhR, g_WhhR);

    cudaFuncSetAttribute(k_lstm_persist, cudaFuncAttributeMaxDynamicSharedMemorySize,
                         PERSIST_SMEM);
    cudaFuncSetAttribute(k_gemm_fp16, cudaFuncAttributeMaxDynamicSharedMemorySize,
                         GEMM_SMEM);

    k_transpose_win<<<(HH * INP + 255) / 256, 256>>>(W_in, winT);
    k_round2<<<(2 * GG * HH + 255) / 256, 256>>>(Wih, wihR, Whh, whhR);
    k_build_feat<<<(MT * INP + 255) / 256, 256>>>(x, smean, sscale, emb, feat);

    // input projection: seq0 = half(relu(feat @ W_in + b_in)), K=192
    {
        dim3 grid(HH / 128, MT / 128);
        k_gemm_fp16<<<grid, 256, GEMM_SMEM>>>(feat, winT, b_in, seq0, MT, HH, INP, 3);
    }

    const __half* seq_in  = seq0;
    __half*       seq_out = seq1;
    for (int l = 0; l < 2; l++) {
        const __half* Wih_l = wihR + (size_t)l * GG * HH;
        const __half* Whh_l = whhR + (size_t)l * GG * HH;
        const float*  bih_l = bih  + (size_t)l * GG;
        const float*  bhh_l = bhh  + (size_t)l * GG;

        // xw = seq_in @ Wih^T + bih  (fp32 output)
        {
            dim3 grid(GG / 128, MT / 128);
            k_gemm_fp16<<<grid, 256, GEMM_SMEM>>>(seq_in, Wih_l, bih_l, xw, MT, GG, HH, 0);
        }
        k_reset<<<(BQ * HH + 255) / 256, 256>>>();
        {
            dim3 grid(HH / 16, BQ / 64);   // (32, 4) = 128 CTAs
            k_lstm_persist<<<grid, 256, PERSIST_SMEM>>>(xw, Whh_l, bhh_l, seq_out,
                                                        (l == 0) ? 1 : 0);
        }
        const __half* tmp_in = seq_out;
        seq_out = (__half*)seq_in;
        seq_in  = tmp_in;
    }

    k_head<<<(BQ * 560 + 255) / 256, 256>>>(seq_in, W_out, b_out, W_cls, b_cls, out);
}

// round 16
// speedup vs baseline: 1.0321x; 1.0007x over previous
#include <cuda_runtime.h>
#include <cuda_fp16.h>
#include <math.h>
#include <stdint.h>

// ---------------- problem constants ----------------
#define BQ     256
#define TT     100
#define NFEAT  64
#define VV     32
#define EE     8
#define HH     512
#define NCAT   16
#define NCONT  48
#define INLEN  176
#define INP    192        // padded K for input projection
#define GG     2048
#define MT     (BQ*TT)

// persist smem (bytes): Bs half[64][520] + Ha half[8][64][72] + Xs half[2][64][72] + Gs f32[2][64][68]
#define P_BS_B   (64*520*2)                 // 66,560
#define P_HA_B   (8*64*72*2)                // 73,728
#define P_XS_B   (2*64*72*2)                // 18,432
#define P_GS_B   (2*64*68*4)                // 34,816
#define P_HA_OFF (P_BS_B)
#define P_XS_OFF (P_BS_B + P_HA_B)
#define P_GS_OFF (P_BS_B + P_HA_B + P_XS_B)
#define PERSIST_SMEM (P_BS_B + P_HA_B + P_XS_B + P_GS_B)   // 193,536 B

// GEMM smem: 4 stages x (A 128x40 + W 128x40) halves
#define ASTG_H   (128*40)
#define ASTG_B   (ASTG_H*2)                 // 10,240 B
#define GEMM_SMEM (4 * 2 * ASTG_B)          // 81,920 B

// ---------------- scratch ----------------
__device__ __half g_feat[MT * INP + 64];
__device__ __half g_seq0[MT * HH + 64];
__device__ __half g_seq1[MT * HH + 64];
__device__ __half g_xw  [(size_t)MT * GG + 64];   // fp16 gate pre-activations
__device__ __half g_WinT[HH * INP + 64];
__device__ __half g_WihR[2 * GG * HH];
__device__ __half g_WhhR[2 * GG * HH];
__device__ __half g_ht  [2 * BQ * HH];      // m-major h state, double buffered
__device__ unsigned g_cnt[4];               // per-m0-group barrier counters
__device__ unsigned g_gen[4];

// ---------------- helpers ----------------
__device__ __forceinline__ void mmah(float* d, const unsigned* a, const unsigned* b) {
    asm volatile("mma.sync.aligned.m16n8k16.row.col.f32.f16.f16.f32 "
                 "{%0,%1,%2,%3}, {%4,%5,%6,%7}, {%8,%9}, {%0,%1,%2,%3};"
                 : "+f"(d[0]), "+f"(d[1]), "+f"(d[2]), "+f"(d[3])
                 : "r"(a[0]), "r"(a[1]), "r"(a[2]), "r"(a[3]), "r"(b[0]), "r"(b[1]));
}

__device__ __forceinline__ void ldsm4(unsigned& r0, unsigned& r1, unsigned& r2, unsigned& r3,
                                      unsigned addr) {
    asm volatile("ldmatrix.sync.aligned.m8n8.x4.shared.b16 {%0,%1,%2,%3}, [%4];"
                 : "=r"(r0), "=r"(r1), "=r"(r2), "=r"(r3) : "r"(addr));
}

__device__ __forceinline__ void cpasync16(void* smem_dst, const void* gsrc) {
    unsigned s = (unsigned)__cvta_generic_to_shared(smem_dst);
    asm volatile("cp.async.cg.shared.global [%0], [%1], 16;" :: "r"(s), "l"(gsrc));
}
__device__ __forceinline__ void cpcommit() { asm volatile("cp.async.commit_group;" ::: "memory"); }
template<int N> __device__ __forceinline__ void cpwaitN() {
    asm volatile("cp.async.wait_group %0;" :: "n"(N) : "memory");
}

__device__ __forceinline__ float sigm(float x)     { return 1.f / (1.f + __expf(-x)); }
__device__ __forceinline__ float tanhfast(float x) { return 2.f / (1.f + __expf(-2.f * x)) - 1.f; }

__device__ __forceinline__ void bar_grp(int khalf) {
    if (khalf == 0) asm volatile("bar.sync 1, 128;" ::: "memory");
    else            asm volatile("bar.sync 2, 128;" ::: "memory");
}

// ---------------- small utility kernels ----------------
__global__ void k_transpose_win(const float* __restrict__ Win, __half* __restrict__ WinT)
{
    int idx = blockIdx.x * blockDim.x + threadIdx.x;   // over HH*INP
    if (idx >= HH * INP) return;
    int n = idx / INP, k = idx % INP;
    WinT[idx] = (k < INLEN) ? __float2half_rn(Win[k * HH + n]) : __float2half_rn(0.f);
}

__global__ void k_round2(const float* __restrict__ A, __half* __restrict__ RA,
                         const float* __restrict__ B, __half* __restrict__ RB)
{
    int i = blockIdx.x * blockDim.x + threadIdx.x;
    if (i < 2 * GG * HH) { RA[i] = __float2half_rn(A[i]); RB[i] = __float2half_rn(B[i]); }
}

__global__ void k_reset()
{
    int i = blockIdx.x * blockDim.x + threadIdx.x;
    if (i < BQ * HH) g_ht[i] = __float2half_rn(0.f);   // only buffer 0 is read at t=0
    if (i < 4) { g_cnt[i] = 0; g_gen[i] = 0; }
}

__global__ void k_build_feat(const float* __restrict__ x,
                             const float* __restrict__ mean,
                             const float* __restrict__ scale,
                             const float* __restrict__ emb,
                             __half* __restrict__ feat)
{
    int idx = blockIdx.x * blockDim.x + threadIdx.x;   // over MT*INP
    if (idx >= MT * INP) return;
    int c = idx % INP;
    int m = idx / INP;
    float v = 0.f;
    if (c < INLEN) {
        int blk = c / 11, r = c % 11;
        if (r < 8) {
            int k  = 4 * blk;
            int xi = (int)x[(size_t)m * NFEAT + k];
            v = emb[((size_t)blk * VV + xi) * EE + r];
        } else {
            int k = 4 * blk + (r - 7);
            v = (x[(size_t)m * NFEAT + k] - mean[k]) / scale[k];
        }
    }
    feat[idx] = __float2half_rn(v);
}

// ---------------- fp16 NT GEMM: 128x128 CTA, 8 warps of 32x64, BK=32(half), 4-stage ----
__device__ __forceinline__ void gemm_load_stage(__half* dstA, __half* dstW,
                                                const __half* A, const __half* W,
                                                int bm, int bn, int K, int k0, int tid)
{
#pragma unroll
    for (int i = 0; i < 2; i++) {
        int e   = tid + i * 256;      // 0..511
        int row = e >> 2;             // 0..127
        int q   = (e & 3) << 3;       // 0,8,16,24 halves
        cpasync16(dstA + row * 40 + q, A + (size_t)(bm + row) * K + k0 + q);
    }
#pragma unroll
    for (int i = 0; i < 2; i++) {
        int e   = tid + i * 256;
        int row = e >> 2;
        int q   = (e & 3) << 3;
        cpasync16(dstW + row * 40 + q, W + (size_t)(bn + row) * K + k0 + q);
    }
}

__global__ __launch_bounds__(256, 2)
void k_gemm_fp16(const __half* __restrict__ A, const __half* __restrict__ W,
                 const float* __restrict__ bias, void* __restrict__ Cv,
                 int M, int N, int K, int flags)   // bit0: relu, bit1: half output
{
    extern __shared__ __half smh[];
    __half* As = smh;                       // [4][128*40]
    __half* Ws = smh + 4 * ASTG_H;

    const int tid  = threadIdx.x;
    const int bm   = blockIdx.y * 128;
    const int bn   = blockIdx.x * 128;
    const int lane = tid & 31, warp = tid >> 5;
    const int wm   = (warp & 3) * 32;       // 4 m-warps, tile 32
    const int wn   = (warp >> 2) * 64;      // 2 n-warps, tile 64
    const int r    = lane >> 2, cq = lane & 3;
    const int NK   = K >> 5;                // K % 32 == 0, NK >= 3

    const unsigned sbg = (unsigned)__cvta_generic_to_shared(smh);
    const int arow = lane & 15;
    const int kA   = (lane & 16) ? 8 : 0;   // halves
    const int brow = (lane & 7) + ((lane & 16) ? 8 : 0);
    const int kB   = (lane & 8) ? 8 : 0;    // halves
    const unsigned aoff = ((wm + arow) * 40 + kA) * 2;
    const unsigned boff = ((wn + brow) * 40 + kB) * 2;

    float acc[2][8][4];
#pragma unroll
    for (int mt = 0; mt < 2; mt++)
#pragma unroll
        for (int in = 0; in < 8; in++)
#pragma unroll
            for (int q = 0; q < 4; q++) acc[mt][in][q] = 0.f;

    gemm_load_stage(As, Ws, A, W, bm, bn, K, 0, tid); cpcommit();
    gemm_load_stage(As + ASTG_H, Ws + ASTG_H, A, W, bm, bn, K, 32, tid); cpcommit();
    gemm_load_stage(As + 2 * ASTG_H, Ws + 2 * ASTG_H, A, W, bm, bn, K, 64, tid); cpcommit();

    for (int kc = 0; kc < NK; kc++) {
        if      (kc < NK - 2) cpwaitN<2>();
        else if (kc < NK - 1) cpwaitN<1>();
        else                  cpwaitN<0>();
        __syncthreads();
        if (kc + 3 < NK) {
            int s = (kc + 3) & 3;
            gemm_load_stage(As + s * ASTG_H, Ws + s * ASTG_H, A, W, bm, bn, K,
                            (kc + 3) << 5, tid);
            cpcommit();
        }
        const unsigned asb = sbg + (kc & 3) * ASTG_B;
        const unsigned wsb = sbg + 4 * ASTG_B + (kc & 3) * ASTG_B;
#pragma unroll
        for (int kk = 0; kk < 32; kk += 16) {
            unsigned a[2][4], b[8][2];
#pragma unroll
            for (int mt = 0; mt < 2; mt++)
                ldsm4(a[mt][0], a[mt][1], a[mt][2], a[mt][3],
                      asb + aoff + (mt * 16 * 40 + kk) * 2);
#pragma unroll
            for (int p = 0; p < 4; p++) {
                unsigned t0, t1, t2, t3;
                ldsm4(t0, t1, t2, t3, wsb + boff + (p * 16 * 40 + kk) * 2);
                b[2 * p][0] = t0; b[2 * p][1] = t1;
                b[2 * p + 1][0] = t2; b[2 * p + 1][1] = t3;
            }
#pragma unroll
            for (int mt = 0; mt < 2; mt++)
#pragma unroll
                for (int in = 0; in < 8; in++)
                    mmah(acc[mt][in], a[mt], b[in]);
        }
    }

    const int doRelu = flags & 1;
    const int doHalf = flags & 2;
#pragma unroll
    for (int mt = 0; mt < 2; mt++) {
        int row = bm + wm + mt * 16 + r;
#pragma unroll
        for (int in = 0; in < 8; in++) {
            int col = bn + wn + in * 8 + 2 * cq;
            float2 bv = *(const float2*)(bias + col);
            float v0 = acc[mt][in][0] + bv.x;
            float v1 = acc[mt][in][1] + bv.y;
            float v2 = acc[mt][in][2] + bv.x;
            float v3 = acc[mt][in][3] + bv.y;
            if (doRelu) {
                v0 = fmaxf(v0, 0.f); v1 = fmaxf(v1, 0.f);
                v2 = fmaxf(v2, 0.f); v3 = fmaxf(v3, 0.f);
            }
            if (doHalf) {
                __half* C = (__half*)Cv;
                *(__half2*)(C + (size_t)row * N + col) =
                    __floats2half2_rn(v0, v1);
                *(__half2*)(C + (size_t)(row + 8) * N + col) =
                    __floats2half2_rn(v2, v3);
            } else {
                float* C = (float*)Cv;
                *(float2*)(C + (size_t)row * N + col)       = make_float2(v0, v1);
                *(float2*)(C + (size_t)(row + 8) * N + col) = make_float2(v2, v3);
            }
        }
    }
}

// ---------------- persistent recurrent LSTM layer (fp16, 4-wave h fetch, fp16 xw) ----
__device__ __forceinline__ void load_h_wave(__half* Ha, const __half* ht_in,
                                            int m0, int khalf, int wave, int gtid)
{
#pragma unroll
    for (int i = 0; i < 4; i++) {
        int s   = gtid + i * 128;        // 0..511
        int row = s >> 3;                // 0..63
        int c8  = (s & 7) << 3;
        int chunk = khalf * 4 + wave;
        cpasync16(Ha + (size_t)chunk * (64 * 72) + row * 72 + c8,
                  ht_in + (size_t)(m0 + row) * HH + chunk * 64 + c8);
    }
}

__device__ __forceinline__ void load_xs(__half* dst, const __half* xw,
                                        int t, int m0, int j0, int tid)
{
#pragma unroll
    for (int i = 0; i < 2; i++) {
        int s   = tid + i * 256;      // 0..511
        int row = s >> 3;             // 0..63
        int q   = (s >> 1) & 3;
        int f8  = (s & 1) << 3;       // 0 or 8 halves
        cpasync16(dst + row * 72 + q * 16 + f8,
                  xw + ((size_t)(m0 + row) * TT + t) * GG + q * HH + j0 + f8);
    }
}

__global__ __launch_bounds__(256, 1)
void k_lstm_persist(const __half* __restrict__ xw, const __half* __restrict__ WhhR,
                    const float* __restrict__ bhh, __half* __restrict__ seq_out,
                    int writeAll)
{
    extern __shared__ char smc[];
    __half* Bs = (__half*)smc;                    // [64][520] Whh slice
    __half* Ha = (__half*)(smc + P_HA_OFF);       // [8][64][72] h chunks (all resident)
    __half* Xs = (__half*)(smc + P_XS_OFF);       // [2][64][72] xw tiles (fp16)
    float*  Gs = (float*)(smc + P_GS_OFF);        // [2][64][68] split-K partials

    const int tid   = threadIdx.x, lane = tid & 31, warp = tid >> 5;
    const int j0    = blockIdx.x * 16;
    const int m0    = blockIdx.y * 64;
    const int grp   = blockIdx.y;                 // barrier group (32 CTAs)
    const int khalf = warp >> 2;
    const int gtid  = tid & 127;
    const int wmw   = (warp & 1) * 32;
    const int wnw   = ((warp >> 1) & 1) * 32;
    const int jjt   = tid & 15;
    const int mgt   = tid >> 4;

    const unsigned sbB  = (unsigned)__cvta_generic_to_shared(Bs);
    const unsigned sbHa = (unsigned)__cvta_generic_to_shared(Ha);
    const int arow = lane & 15;
    const int kA   = (lane & 16) ? 8 : 0;
    const int brow = (lane & 7) + ((lane & 16) ? 8 : 0);
    const int kB   = (lane & 8) ? 8 : 0;
    const unsigned aoff = ((wmw + arow) * 72 + kA) * 2;
    const unsigned boff = ((wnw + brow) * 520 + kB) * 2;

    // one-time Bs load: row n = jj*4+q <- WhhR row q*512+j0+jj, full K (512 halves)
    {
#pragma unroll
        for (int i = 0; i < 16; i++) {
            int s  = tid + i * 256;       // 0..4095
            int n  = s >> 6;              // 0..63
            int c8 = (s & 63) << 3;       // 0..504
            int jj = n >> 2, q = n & 3;
            cpasync16(Bs + n * 520 + c8, WhhR + (size_t)(q * HH + j0 + jj) * HH + c8);
        }
        cpcommit();
    }
    float bh[4];
#pragma unroll
    for (int q = 0; q < 4; q++) bh[q] = bhh[q * HH + j0 + jjt];

    float cst[4] = {0.f, 0.f, 0.f, 0.f};

    // prologue: drain Bs, then commit xw(0), 4 h-waves
    cpwaitN<0>();
    __syncthreads();
    load_xs(Xs, xw, 0, m0, j0, tid);                cpcommit();
#pragma unroll
    for (int w = 0; w < 4; w++) { load_h_wave(Ha, g_ht, m0, khalf, w, gtid); cpcommit(); }

    for (int t = 0; t < TT; t++) {
        float acc[2][4][4];
#pragma unroll
        for (int mt = 0; mt < 2; mt++)
#pragma unroll
            for (int in = 0; in < 4; in++)
#pragma unroll
                for (int q = 0; q < 4; q++) acc[mt][in][q] = 0.f;

        // pending (oldest first): xw(t), w0, w1, w2, w3
#pragma unroll
        for (int cl = 0; cl < 4; cl++) {
            if      (cl == 0) cpwaitN<3>();   // drains xw(t) + w0
            else if (cl == 1) cpwaitN<2>();
            else if (cl == 2) cpwaitN<1>();
            else              cpwaitN<0>();
            bar_grp(khalf);
            const int chunk = khalf * 4 + cl;
            const unsigned hb = sbHa + (unsigned)(chunk * 64 * 72 * 2);
            const int kg0 = chunk * 64;
#pragma unroll
            for (int kk = 0; kk < 64; kk += 16) {
                unsigned a[2][4];
#pragma unroll
                for (int mt = 0; mt < 2; mt++)
                    ldsm4(a[mt][0], a[mt][1], a[mt][2], a[mt][3],
                          hb + aoff + (mt * 16 * 72 + kk) * 2);
                unsigned b[4][2];
#pragma unroll
                for (int p = 0; p < 2; p++) {
                    unsigned t0, t1, t2, t3;
                    ldsm4(t0, t1, t2, t3,
                          sbB + boff + (p * 16 * 520 + kg0 + kk) * 2);
                    b[2 * p][0] = t0; b[2 * p][1] = t1;
                    b[2 * p + 1][0] = t2; b[2 * p + 1][1] = t3;
                }
#pragma unroll
                for (int mt = 0; mt < 2; mt++)
#pragma unroll
                    for (int in = 0; in < 4; in++)
                        mmah(acc[mt][in], a[mt], b[in]);
            }
        }

        // commit next step's xw tile early (overlaps merge + epilogue + barrier)
        if (t + 1 < TT) { load_xs(Xs + ((t + 1) & 1) * (64 * 72), xw, t + 1, m0, j0, tid); cpcommit(); }

        // write split-K partials (disjoint per khalf)
        {
            const int r = lane >> 2, cq = lane & 3;
            float* G = Gs + khalf * (64 * 68);
#pragma unroll
            for (int mt = 0; mt < 2; mt++) {
                int row = wmw + mt * 16 + r;
#pragma unroll
                for (int in = 0; in < 4; in++) {
                    int col = wnw + in * 8 + 2 * cq;
                    *(float2*)&G[row * 68 + col]       = make_float2(acc[mt][in][0], acc[mt][in][1]);
                    *(float2*)&G[(row + 8) * 68 + col] = make_float2(acc[mt][in][2], acc[mt][in][3]);
                }
            }
        }
        __syncthreads();

        // epilogue: thread (jjt, m = mgt+16*it); keep hv in regs, store only ht_out now
        const int pin = t & 1;
        __half* ht_out = g_ht + (size_t)(pin ^ 1) * (BQ * HH);
        const __half* xs = Xs + (t & 1) * (64 * 72);
        const float* GsA = Gs;
        const float* GsB = Gs + 64 * 68;
        float hvreg[4];
#pragma unroll
        for (int it = 0; it < 4; it++) {
            int m = mgt + it * 16;
            float4 ga = *(const float4*)&GsA[m * 68 + jjt * 4];
            float4 gb = *(const float4*)&GsB[m * 68 + jjt * 4];
            float gi = ga.x + gb.x + __half2float(xs[m * 72 +      jjt]) + bh[0];
            float gf = ga.y + gb.y + __half2float(xs[m * 72 + 16 + jjt]) + bh[1];
            float gg = ga.z + gb.z + __half2float(xs[m * 72 + 32 + jjt]) + bh[2];
            float go = ga.w + gb.w + __half2float(xs[m * 72 + 48 + jjt]) + bh[3];
            float iv = sigm(gi), fv = sigm(gf);
            float gv = tanhfast(gg), ov = sigm(go);
            float cv = fv * cst[it] + iv * gv;
            cst[it] = cv;
            float hv = ov * tanhfast(cv);
            hvreg[it] = hv;
            ht_out[(size_t)(m0 + m) * HH + j0 + jjt] = __float2half_rn(hv);
        }

        // per-m0-group barrier (32 CTAs), last-arriver release, cumulative counts
        __threadfence();
        __syncthreads();
        if (tid == 0) {
            unsigned old = atomicAdd(&g_cnt[grp], 1u);
            if (old == 32u * (unsigned)(t + 1) - 1u) {
                __threadfence();
                *(volatile unsigned*)&g_gen[grp] = (unsigned)(t + 1);
            } else {
                while (*(volatile unsigned*)&g_gen[grp] < (unsigned)(t + 1)) { }
                __threadfence();
            }
        }
        __syncthreads();

        // issue H(t+1) waves first, then deferred seq stores (off critical path)
        if (t + 1 < TT) {
            const __half* hin2 = g_ht + (size_t)((t + 1) & 1) * (BQ * HH);
#pragma unroll
            for (int w = 0; w < 4; w++) { load_h_wave(Ha, hin2, m0, khalf, w, gtid); cpcommit(); }
        }
        if (writeAll | (t == TT - 1)) {
#pragma unroll
            for (int it = 0; it < 4; it++) {
                int m = mgt + it * 16;
                seq_out[((size_t)(m0 + m) * TT + t) * HH + j0 + jjt] =
                    __float2half_rn(fmaxf(hvreg[it], 0.f));
            }
        }
    }
}

// ---------------- heads ----------------
__global__ void k_head(const __half* __restrict__ seq,
                       const float* __restrict__ W_out, const float* __restrict__ b_out,
                       const float* __restrict__ W_cls, const float* __restrict__ b_cls,
                       float* __restrict__ out)
{
    int idx = blockIdx.x * blockDim.x + threadIdx.x;
    if (idx >= BQ * 560) return;
    int b = idx / 560, c = idx % 560;
    const __half* last = seq + ((size_t)b * TT + (TT - 1)) * HH;
    if (c < NCONT) {
        float s = b_out[c];
#pragma unroll 4
        for (int k = 0; k < HH; k++) s += __half2float(last[k]) * W_out[k * NCONT + c];
        out[b * NCONT + c] = s;
    } else {
        int cc = c - NCONT;
        int n = cc >> 5, v = cc & 31;
        float s = b_cls[n * VV + v];
        const float* w = W_cls + (size_t)n * HH * VV + v;
#pragma unroll 4
        for (int k = 0; k < HH; k++) s += __half2float(last[k]) * w[k * VV];
        out[BQ * NCONT + (size_t)b * (NCAT * VV) + cc] = s;
    }
}

// ---------------- launch ----------------
extern "C" void kernel_launch(void* const* d_in, const int* in_sizes, int n_in,
                              void* d_out, int out_size)
{
    const float* x      = (const float*)d_in[0];
    const float* smean  = (const float*)d_in[1];
    const float* sscale = (const float*)d_in[2];
    const float* emb    = (const float*)d_in[3];
    const float* W_in   = (const float*)d_in[4];
    const float* b_in   = (const float*)d_in[5];
    const float* Wih    = (const float*)d_in[6];
    const float* Whh    = (const float*)d_in[7];
    const float* bih    = (const float*)d_in[8];
    const float* bhh    = (const float*)d_in[9];
    const float* W_out  = (const float*)d_in[10];
    const float* b_out  = (const float*)d_in[11];
    const float* W_cls  = (const float*)d_in[12];
    const float* b_cls  = (const float*)d_in[13];
    float* out = (float*)d_out;

    __half *feat, *seq0, *seq1, *winT, *wihR, *whhR, *xw;
    cudaGetSymbolAddress((void**)&feat, g_feat);
    cudaGetSymbolAddress((void**)&seq0, g_seq0);
    cudaGetSymbolAddress((void**)&seq1, g_seq1);
    cudaGetSymbolAddress((void**)&xw,   g_xw);
    cudaGetSymbolAddress((void**)&winT, g_WinT);
    cudaGetSymbolAddress((void**)&wihR, g_WihR);
    cudaGetSymbolAddress((void**)&whhR, g_WhhR);

    cudaFuncSetAttribute(k_lstm_persist, cudaFuncAttributeMaxDynamicSharedMemorySize,
                         PERSIST_SMEM);
    cudaFuncSetAttribute(k_gemm_fp16, cudaFuncAttributeMaxDynamicSharedMemorySize,
                         GEMM_SMEM);

    k_transpose_win<<<(HH * INP + 255) / 256, 256>>>(W_in, winT);
    k_round2<<<(2 * GG * HH + 255) / 256, 256>>>(Wih, wihR, Whh, whhR);
    k_build_feat<<<(MT * INP + 255) / 256, 256>>>(x, smean, sscale, emb, feat);

    // input projection: seq0 = half(relu(feat @ W_in + b_in)), K=192
    {
        dim3 grid(HH / 128, MT / 128);
        k_gemm_fp16<<<grid, 256, GEMM_SMEM>>>(feat, winT, b_in, seq0, MT, HH, INP, 3);
    }

    const __half* seq_in  = seq0;
    __half*       seq_out = seq1;
    for (int l = 0; l < 2; l++) {
        const __half* Wih_l = wihR + (size_t)l * GG * HH;
        const __half* Whh_l = whhR + (size_t)l * GG * HH;
        const float*  bih_l = bih  + (size_t)l * GG;
        const float*  bhh_l = bhh  + (size_t)l * GG;

        // xw = seq_in @ Wih^T + bih  (fp16 output)
        {
            dim3 grid(GG / 128, MT / 128);
            k_gemm_fp16<<<grid, 256, GEMM_SMEM>>>(seq_in, Wih_l, bih_l, xw, MT, GG, HH, 2);
        }
        k_reset<<<(BQ * HH + 255) / 256, 256>>>();
        {
            dim3 grid(HH / 16, BQ / 64);   // (32, 4) = 128 CTAs
            k_lstm_persist<<<grid, 256, PERSIST_SMEM>>>(xw, Whh_l, bhh_l, seq_out,
                                                        (l == 0) ? 1 : 0);
        }
        const __half* tmp_in = seq_out;
        seq_out = (__half*)seq_in;
        seq_in  = tmp_in;
    }

    k_head<<<(BQ * 560 + 255) / 256, 256>>>(seq_in, W_out, b_out, W_cls, b_cls, out);
}

// round 17
// speedup vs baseline: 1.0530x; 1.0203x over previous
#include <cuda_runtime.h>
#include <cuda_fp16.h>
#include <math.h>
#include <stdint.h>

// ---------------- problem constants ----------------
#define BQ     256
#define TT     100
#define NFEAT  64
#define VV     32
#define EE     8
#define HH     512
#define NCAT   16
#define NCONT  48
#define INLEN  176
#define INP    192        // padded K for input projection
#define GG     2048
#define MT     (BQ*TT)

// persist smem (bytes): Bs half[64][520] + Ha half[8][64][72] + Xs half[2][64][72] + Gs f32[2][64][68]
#define P_BS_B   (64*520*2)                 // 66,560
#define P_HA_B   (8*64*72*2)                // 73,728
#define P_XS_B   (2*64*72*2)                // 18,432
#define P_GS_B   (2*64*68*4)                // 34,816
#define P_HA_OFF (P_BS_B)
#define P_XS_OFF (P_BS_B + P_HA_B)
#define P_GS_OFF (P_BS_B + P_HA_B + P_XS_B)
#define PERSIST_SMEM (P_BS_B + P_HA_B + P_XS_B + P_GS_B)   // 193,536 B

// GEMM smem: 4 stages x (A 128x40 + W 128x40) halves
#define ASTG_H   (128*40)
#define ASTG_B   (ASTG_H*2)                 // 10,240 B
#define GEMM_SMEM (4 * 2 * ASTG_B)          // 81,920 B

// ---------------- scratch ----------------
__device__ __half g_feat[MT * INP + 64];
__device__ __half g_seq0[MT * HH + 64];
__device__ __half g_seq1[MT * HH + 64];
__device__ __half g_xw  [(size_t)MT * GG + 64];   // fp16 gate pre-activations
__device__ __half g_WinT[HH * INP + 64];
__device__ __half g_WihR[2 * GG * HH];
__device__ __half g_WhhR[2 * GG * HH];
__device__ __half g_ht  [2 * BQ * HH];      // m-major h state, double buffered
__device__ unsigned g_cnt[4];               // per-m0-group barrier counters
__device__ unsigned g_gen[4];

// ---------------- helpers ----------------
__device__ __forceinline__ void mmah(float* d, const unsigned* a, const unsigned* b) {
    asm volatile("mma.sync.aligned.m16n8k16.row.col.f32.f16.f16.f32 "
                 "{%0,%1,%2,%3}, {%4,%5,%6,%7}, {%8,%9}, {%0,%1,%2,%3};"
                 : "+f"(d[0]), "+f"(d[1]), "+f"(d[2]), "+f"(d[3])
                 : "r"(a[0]), "r"(a[1]), "r"(a[2]), "r"(a[3]), "r"(b[0]), "r"(b[1]));
}

__device__ __forceinline__ void ldsm4(unsigned& r0, unsigned& r1, unsigned& r2, unsigned& r3,
                                      unsigned addr) {
    asm volatile("ldmatrix.sync.aligned.m8n8.x4.shared.b16 {%0,%1,%2,%3}, [%4];"
                 : "=r"(r0), "=r"(r1), "=r"(r2), "=r"(r3) : "r"(addr));
}

__device__ __forceinline__ void cpasync16(void* smem_dst, const void* gsrc) {
    unsigned s = (unsigned)__cvta_generic_to_shared(smem_dst);
    asm volatile("cp.async.cg.shared.global [%0], [%1], 16;" :: "r"(s), "l"(gsrc));
}
__device__ __forceinline__ void cpcommit() { asm volatile("cp.async.commit_group;" ::: "memory"); }
template<int N> __device__ __forceinline__ void cpwaitN() {
    asm volatile("cp.async.wait_group %0;" :: "n"(N) : "memory");
}

__device__ __forceinline__ float sigm(float x)     { return 1.f / (1.f + __expf(-x)); }
__device__ __forceinline__ float tanhfast(float x) { return 2.f / (1.f + __expf(-2.f * x)) - 1.f; }

__device__ __forceinline__ void bar_grp(int khalf) {
    if (khalf == 0) asm volatile("bar.sync 1, 256;" ::: "memory");
    else            asm volatile("bar.sync 2, 256;" ::: "memory");
}

// ---------------- small utility kernels ----------------
__global__ void k_transpose_win(const float* __restrict__ Win, __half* __restrict__ WinT)
{
    int idx = blockIdx.x * blockDim.x + threadIdx.x;   // over HH*INP
    if (idx >= HH * INP) return;
    int n = idx / INP, k = idx % INP;
    WinT[idx] = (k < INLEN) ? __float2half_rn(Win[k * HH + n]) : __float2half_rn(0.f);
}

__global__ void k_round2(const float* __restrict__ A, __half* __restrict__ RA,
                         const float* __restrict__ B, __half* __restrict__ RB)
{
    int i = blockIdx.x * blockDim.x + threadIdx.x;
    if (i < 2 * GG * HH) { RA[i] = __float2half_rn(A[i]); RB[i] = __float2half_rn(B[i]); }
}

__global__ void k_reset()
{
    int i = blockIdx.x * blockDim.x + threadIdx.x;
    if (i < BQ * HH) g_ht[i] = __float2half_rn(0.f);   // only buffer 0 is read at t=0
    if (i < 4) { g_cnt[i] = 0; g_gen[i] = 0; }
}

__global__ void k_build_feat(const float* __restrict__ x,
                             const float* __restrict__ mean,
                             const float* __restrict__ scale,
                             const float* __restrict__ emb,
                             __half* __restrict__ feat)
{
    int idx = blockIdx.x * blockDim.x + threadIdx.x;   // over MT*INP
    if (idx >= MT * INP) return;
    int c = idx % INP;
    int m = idx / INP;
    float v = 0.f;
    if (c < INLEN) {
        int blk = c / 11, r = c % 11;
        if (r < 8) {
            int k  = 4 * blk;
            int xi = (int)x[(size_t)m * NFEAT + k];
            v = emb[((size_t)blk * VV + xi) * EE + r];
        } else {
            int k = 4 * blk + (r - 7);
            v = (x[(size_t)m * NFEAT + k] - mean[k]) / scale[k];
        }
    }
    feat[idx] = __float2half_rn(v);
}

// ---------------- fp16 NT GEMM: 128x128 CTA, 8 warps of 32x64, BK=32(half), 4-stage ----
__device__ __forceinline__ void gemm_load_stage(__half* dstA, __half* dstW,
                                                const __half* A, const __half* W,
                                                int bm, int bn, int K, int k0, int tid)
{
#pragma unroll
    for (int i = 0; i < 2; i++) {
        int e   = tid + i * 256;      // 0..511
        int row = e >> 2;             // 0..127
        int q   = (e & 3) << 3;       // 0,8,16,24 halves
        cpasync16(dstA + row * 40 + q, A + (size_t)(bm + row) * K + k0 + q);
    }
#pragma unroll
    for (int i = 0; i < 2; i++) {
        int e   = tid + i * 256;
        int row = e >> 2;
        int q   = (e & 3) << 3;
        cpasync16(dstW + row * 40 + q, W + (size_t)(bn + row) * K + k0 + q);
    }
}

__global__ __launch_bounds__(256, 2)
void k_gemm_fp16(const __half* __restrict__ A, const __half* __restrict__ W,
                 const float* __restrict__ bias, void* __restrict__ Cv,
                 int M, int N, int K, int flags)   // bit0: relu, bit1: half output
{
    extern __shared__ __half smh[];
    __half* As = smh;                       // [4][128*40]
    __half* Ws = smh + 4 * ASTG_H;

    const int tid  = threadIdx.x;
    const int bm   = blockIdx.y * 128;
    const int bn   = blockIdx.x * 128;
    const int lane = tid & 31, warp = tid >> 5;
    const int wm   = (warp & 3) * 32;       // 4 m-warps, tile 32
    const int wn   = (warp >> 2) * 64;      // 2 n-warps, tile 64
    const int r    = lane >> 2, cq = lane & 3;
    const int NK   = K >> 5;                // K % 32 == 0, NK >= 3

    const unsigned sbg = (unsigned)__cvta_generic_to_shared(smh);
    const int arow = lane & 15;
    const int kA   = (lane & 16) ? 8 : 0;   // halves
    const int brow = (lane & 7) + ((lane & 16) ? 8 : 0);
    const int kB   = (lane & 8) ? 8 : 0;    // halves
    const unsigned aoff = ((wm + arow) * 40 + kA) * 2;
    const unsigned boff = ((wn + brow) * 40 + kB) * 2;

    float acc[2][8][4];
#pragma unroll
    for (int mt = 0; mt < 2; mt++)
#pragma unroll
        for (int in = 0; in < 8; in++)
#pragma unroll
            for (int q = 0; q < 4; q++) acc[mt][in][q] = 0.f;

    gemm_load_stage(As, Ws, A, W, bm, bn, K, 0, tid); cpcommit();
    gemm_load_stage(As + ASTG_H, Ws + ASTG_H, A, W, bm, bn, K, 32, tid); cpcommit();
    gemm_load_stage(As + 2 * ASTG_H, Ws + 2 * ASTG_H, A, W, bm, bn, K, 64, tid); cpcommit();

    for (int kc = 0; kc < NK; kc++) {
        if      (kc < NK - 2) cpwaitN<2>();
        else if (kc < NK - 1) cpwaitN<1>();
        else                  cpwaitN<0>();
        __syncthreads();
        if (kc + 3 < NK) {
            int s = (kc + 3) & 3;
            gemm_load_stage(As + s * ASTG_H, Ws + s * ASTG_H, A, W, bm, bn, K,
                            (kc + 3) << 5, tid);
            cpcommit();
        }
        const unsigned asb = sbg + (kc & 3) * ASTG_B;
        const unsigned wsb = sbg + 4 * ASTG_B + (kc & 3) * ASTG_B;
#pragma unroll
        for (int kk = 0; kk < 32; kk += 16) {
            unsigned a[2][4], b[8][2];
#pragma unroll
            for (int mt = 0; mt < 2; mt++)
                ldsm4(a[mt][0], a[mt][1], a[mt][2], a[mt][3],
                      asb + aoff + (mt * 16 * 40 + kk) * 2);
#pragma unroll
            for (int p = 0; p < 4; p++) {
                unsigned t0, t1, t2, t3;
                ldsm4(t0, t1, t2, t3, wsb + boff + (p * 16 * 40 + kk) * 2);
                b[2 * p][0] = t0; b[2 * p][1] = t1;
                b[2 * p + 1][0] = t2; b[2 * p + 1][1] = t3;
            }
#pragma unroll
            for (int mt = 0; mt < 2; mt++)
#pragma unroll
                for (int in = 0; in < 8; in++)
                    mmah(acc[mt][in], a[mt], b[in]);
        }
    }

    const int doRelu = flags & 1;
    const int doHalf = flags & 2;
#pragma unroll
    for (int mt = 0; mt < 2; mt++) {
        int row = bm + wm + mt * 16 + r;
#pragma unroll
        for (int in = 0; in < 8; in++) {
            int col = bn + wn + in * 8 + 2 * cq;
            float2 bv = *(const float2*)(bias + col);
            float v0 = acc[mt][in][0] + bv.x;
            float v1 = acc[mt][in][1] + bv.y;
            float v2 = acc[mt][in][2] + bv.x;
            float v3 = acc[mt][in][3] + bv.y;
            if (doRelu) {
                v0 = fmaxf(v0, 0.f); v1 = fmaxf(v1, 0.f);
                v2 = fmaxf(v2, 0.f); v3 = fmaxf(v3, 0.f);
            }
            if (doHalf) {
                __half* C = (__half*)Cv;
                *(__half2*)(C + (size_t)row * N + col) =
                    __floats2half2_rn(v0, v1);
                *(__half2*)(C + (size_t)(row + 8) * N + col) =
                    __floats2half2_rn(v2, v3);
            } else {
                float* C = (float*)Cv;
                *(float2*)(C + (size_t)row * N + col)       = make_float2(v0, v1);
                *(float2*)(C + (size_t)(row + 8) * N + col) = make_float2(v2, v3);
            }
        }
    }
}

// ---------------- persistent recurrent LSTM layer (fp16, 512 threads / 16 warps) ----
// 128 CTAs = 4 batch-tiles(64) x 32 j-tiles(16). 16 warps: 2-way split-K groups of
// 8 warps (4m x 2n tiles of 16x32). 4-wave h fetch; Gs merge; deferred seq stores.

__device__ __forceinline__ void load_h_wave(__half* Ha, const __half* ht_in,
                                            int m0, int khalf, int wave, int gtid)
{
#pragma unroll
    for (int i = 0; i < 2; i++) {
        int s   = gtid + i * 256;        // 0..511
        int row = s >> 3;                // 0..63
        int c8  = (s & 7) << 3;
        int chunk = khalf * 4 + wave;
        cpasync16(Ha + (size_t)chunk * (64 * 72) + row * 72 + c8,
                  ht_in + (size_t)(m0 + row) * HH + chunk * 64 + c8);
    }
}

__device__ __forceinline__ void load_xs(__half* dst, const __half* xw,
                                        int t, int m0, int j0, int tid)
{
    int row = tid >> 3;              // 0..63
    int q   = (tid >> 1) & 3;
    int f8  = (tid & 1) << 3;
    cpasync16(dst + row * 72 + q * 16 + f8,
              xw + ((size_t)(m0 + row) * TT + t) * GG + q * HH + j0 + f8);
}

__global__ __launch_bounds__(512, 1)
void k_lstm_persist(const __half* __restrict__ xw, const __half* __restrict__ WhhR,
                    const float* __restrict__ bhh, __half* __restrict__ seq_out,
                    int writeAll)
{
    extern __shared__ char smc[];
    __half* Bs = (__half*)smc;                    // [64][520] Whh slice
    __half* Ha = (__half*)(smc + P_HA_OFF);       // [8][64][72] h chunks
    __half* Xs = (__half*)(smc + P_XS_OFF);       // [2][64][72] xw tiles (fp16)
    float*  Gs = (float*)(smc + P_GS_OFF);        // [2][64][68] split-K partials

    const int tid   = threadIdx.x, lane = tid & 31, warp = tid >> 5;
    const int j0    = blockIdx.x * 16;
    const int m0    = blockIdx.y * 64;
    const int grp   = blockIdx.y;                 // barrier group (32 CTAs)
    const int khalf = warp >> 3;                  // 0,1 (8 warps each)
    const int wg    = warp & 7;
    const int gtid  = tid & 255;
    const int wmw   = (wg & 3) * 16;              // 4 m-warps, tile 16
    const int wnw   = (wg >> 2) * 32;             // 2 n-warps, tile 32
    const int jjt   = tid & 15;
    const int mgt   = tid >> 4;                   // 0..31

    const unsigned sbB  = (unsigned)__cvta_generic_to_shared(Bs);
    const unsigned sbHa = (unsigned)__cvta_generic_to_shared(Ha);
    const int arow = lane & 15;
    const int kA   = (lane & 16) ? 8 : 0;
    const int brow = (lane & 7) + ((lane & 16) ? 8 : 0);
    const int kB   = (lane & 8) ? 8 : 0;
    const unsigned aoff = ((wmw + arow) * 72 + kA) * 2;
    const unsigned boff = ((wnw + brow) * 520 + kB) * 2;

    // one-time Bs load: row n = jj*4+q <- WhhR row q*512+j0+jj, full K (512 halves)
    {
#pragma unroll
        for (int i = 0; i < 8; i++) {
            int s  = tid + i * 512;       // 0..4095
            int n  = s >> 6;              // 0..63
            int c8 = (s & 63) << 3;       // 0..504
            int jj = n >> 2, q = n & 3;
            cpasync16(Bs + n * 520 + c8, WhhR + (size_t)(q * HH + j0 + jj) * HH + c8);
        }
        cpcommit();
    }
    float bh[4];
#pragma unroll
    for (int q = 0; q < 4; q++) bh[q] = bhh[q * HH + j0 + jjt];

    float cst[2] = {0.f, 0.f};

    // prologue: drain Bs, then commit xw(0), 4 h-waves
    cpwaitN<0>();
    __syncthreads();
    load_xs(Xs, xw, 0, m0, j0, tid);                cpcommit();
#pragma unroll
    for (int w = 0; w < 4; w++) { load_h_wave(Ha, g_ht, m0, khalf, w, gtid); cpcommit(); }

    for (int t = 0; t < TT; t++) {
        float acc[4][4];
#pragma unroll
        for (int in = 0; in < 4; in++)
#pragma unroll
            for (int q = 0; q < 4; q++) acc[in][q] = 0.f;

        // pending (oldest first): xw(t), w0, w1, w2, w3
#pragma unroll
        for (int cl = 0; cl < 4; cl++) {
            if      (cl == 0) cpwaitN<3>();   // drains xw(t) + w0
            else if (cl == 1) cpwaitN<2>();
            else if (cl == 2) cpwaitN<1>();
            else              cpwaitN<0>();
            bar_grp(khalf);
            const int chunk = khalf * 4 + cl;
            const unsigned hb = sbHa + (unsigned)(chunk * 64 * 72 * 2);
            const int kg0 = chunk * 64;
#pragma unroll
            for (int kk = 0; kk < 64; kk += 16) {
                unsigned a[4];
                ldsm4(a[0], a[1], a[2], a[3], hb + aoff + kk * 2);
                unsigned b[4][2];
#pragma unroll
                for (int p = 0; p < 2; p++) {
                    unsigned t0, t1, t2, t3;
                    ldsm4(t0, t1, t2, t3,
                          sbB + boff + (p * 16 * 520 + kg0 + kk) * 2);
                    b[2 * p][0] = t0; b[2 * p][1] = t1;
                    b[2 * p + 1][0] = t2; b[2 * p + 1][1] = t3;
                }
#pragma unroll
                for (int in = 0; in < 4; in++)
                    mmah(acc[in], a, b[in]);
            }
        }

        // commit next step's xw tile early (overlaps merge + epilogue + barrier)
        if (t + 1 < TT) { load_xs(Xs + ((t + 1) & 1) * (64 * 72), xw, t + 1, m0, j0, tid); cpcommit(); }

        // write split-K partials (disjoint per khalf; 8 disjoint 16x32 tiles per group)
        {
            const int r = lane >> 2, cq = lane & 3;
            float* G = Gs + khalf * (64 * 68);
            int row = wmw + r;
#pragma unroll
            for (int in = 0; in < 4; in++) {
                int col = wnw + in * 8 + 2 * cq;
                *(float2*)&G[row * 68 + col]       = make_float2(acc[in][0], acc[in][1]);
                *(float2*)&G[(row + 8) * 68 + col] = make_float2(acc[in][2], acc[in][3]);
            }
        }
        __syncthreads();

        // epilogue: thread (jjt, m = mgt + 32*it); keep hv in regs, store only ht_out now
        const int pin = t & 1;
        __half* ht_out = g_ht + (size_t)(pin ^ 1) * (BQ * HH);
        const __half* xs = Xs + (t & 1) * (64 * 72);
        const float* GsA = Gs;
        const float* GsB = Gs + 64 * 68;
        float hvreg[2];
#pragma unroll
        for (int it = 0; it < 2; it++) {
            int m = mgt + it * 32;
            float4 ga = *(const float4*)&GsA[m * 68 + jjt * 4];
            float4 gb = *(const float4*)&GsB[m * 68 + jjt * 4];
            float gi = ga.x + gb.x + __half2float(xs[m * 72 +      jjt]) + bh[0];
            float gf = ga.y + gb.y + __half2float(xs[m * 72 + 16 + jjt]) + bh[1];
            float gg = ga.z + gb.z + __half2float(xs[m * 72 + 32 + jjt]) + bh[2];
            float go = ga.w + gb.w + __half2float(xs[m * 72 + 48 + jjt]) + bh[3];
            float iv = sigm(gi), fv = sigm(gf);
            float gv = tanhfast(gg), ov = sigm(go);
            float cv = fv * cst[it] + iv * gv;
            cst[it] = cv;
            float hv = ov * tanhfast(cv);
            hvreg[it] = hv;
            ht_out[(size_t)(m0 + m) * HH + j0 + jjt] = __float2half_rn(hv);
        }

        // per-m0-group barrier (32 CTAs), last-arriver release, cumulative counts
        __threadfence();
        __syncthreads();
        if (tid == 0) {
            unsigned old = atomicAdd(&g_cnt[grp], 1u);
            if (old == 32u * (unsigned)(t + 1) - 1u) {
                __threadfence();
                *(volatile unsigned*)&g_gen[grp] = (unsigned)(t + 1);
            } else {
                while (*(volatile unsigned*)&g_gen[grp] < (unsigned)(t + 1)) { }
                __threadfence();
            }
        }
        __syncthreads();

        // issue H(t+1) waves first, then deferred seq stores (off critical path)
        if (t + 1 < TT) {
            const __half* hin2 = g_ht + (size_t)((t + 1) & 1) * (BQ * HH);
#pragma unroll
            for (int w = 0; w < 4; w++) { load_h_wave(Ha, hin2, m0, khalf, w, gtid); cpcommit(); }
        }
        if (writeAll | (t == TT - 1)) {
#pragma unroll
            for (int it = 0; it < 2; it++) {
                int m = mgt + it * 32;
                seq_out[((size_t)(m0 + m) * TT + t) * HH + j0 + jjt] =
                    __float2half_rn(fmaxf(hvreg[it], 0.f));
            }
        }
    }
}

// ---------------- heads ----------------
__global__ void k_head(const __half* __restrict__ seq,
                       const float* __restrict__ W_out, const float* __restrict__ b_out,
                       const float* __restrict__ W_cls, const float* __restrict__ b_cls,
                       float* __restrict__ out)
{
    int idx = blockIdx.x * blockDim.x + threadIdx.x;
    if (idx >= BQ * 560) return;
    int b = idx / 560, c = idx % 560;
    const __half* last = seq + ((size_t)b * TT + (TT - 1)) * HH;
    if (c < NCONT) {
        float s = b_out[c];
#pragma unroll 4
        for (int k = 0; k < HH; k++) s += __half2float(last[k]) * W_out[k * NCONT + c];
        out[b * NCONT + c] = s;
    } else {
        int cc = c - NCONT;
        int n = cc >> 5, v = cc & 31;
        float s = b_cls[n * VV + v];
        const float* w = W_cls + (size_t)n * HH * VV + v;
#pragma unroll 4
        for (int k = 0; k < HH; k++) s += __half2float(last[k]) * w[k * VV];
        out[BQ * NCONT + (size_t)b * (NCAT * VV) + cc] = s;
    }
}

// ---------------- launch ----------------
extern "C" void kernel_launch(void* const* d_in, const int* in_sizes, int n_in,
                              void* d_out, int out_size)
{
    const float* x      = (const float*)d_in[0];
    const float* smean  = (const float*)d_in[1];
    const float* sscale = (const float*)d_in[2];
    const float* emb    = (const float*)d_in[3];
    const float* W_in   = (const float*)d_in[4];
    const float* b_in   = (const float*)d_in[5];
    const float* Wih    = (const float*)d_in[6];
    const float* Whh    = (const float*)d_in[7];
    const float* bih    = (const float*)d_in[8];
    const float* bhh    = (const float*)d_in[9];
    const float* W_out  = (const float*)d_in[10];
    const float* b_out  = (const float*)d_in[11];
    const float* W_cls  = (const float*)d_in[12];
    const float* b_cls  = (const float*)d_in[13];
    float* out = (float*)d_out;

    __half *feat, *seq0, *seq1, *winT, *wihR, *whhR, *xw;
    cudaGetSymbolAddress((void**)&feat, g_feat);
    cudaGetSymbolAddress((void**)&seq0, g_seq0);
    cudaGetSymbolAddress((void**)&seq1, g_seq1);
    cudaGetSymbolAddress((void**)&xw,   g_xw);
    cudaGetSymbolAddress((void**)&winT, g_WinT);
    cudaGetSymbolAddress((void**)&wihR, g_WihR);
    cudaGetSymbolAddress((void**)&whhR, g_WhhR);

    cudaFuncSetAttribute(k_lstm_persist, cudaFuncAttributeMaxDynamicSharedMemorySize,
                         PERSIST_SMEM);
    cudaFuncSetAttribute(k_gemm_fp16, cudaFuncAttributeMaxDynamicSharedMemorySize,
                         GEMM_SMEM);

    k_transpose_win<<<(HH * INP + 255) / 256, 256>>>(W_in, winT);
    k_round2<<<(2 * GG * HH + 255) / 256, 256>>>(Wih, wihR, Whh, whhR);
    k_build_feat<<<(MT * INP + 255) / 256, 256>>>(x, smean, sscale, emb, feat);

    // input projection: seq0 = half(relu(feat @ W_in + b_in)), K=192
    {
        dim3 grid(HH / 128, MT / 128);
        k_gemm_fp16<<<grid, 256, GEMM_SMEM>>>(feat, winT, b_in, seq0, MT, HH, INP, 3);
    }

    const __half* seq_in  = seq0;
    __half*       seq_out = seq1;
    for (int l = 0; l < 2; l++) {
        const __half* Wih_l = wihR + (size_t)l * GG * HH;
        const __half* Whh_l = whhR + (size_t)l * GG * HH;
        const float*  bih_l = bih  + (size_t)l * GG;
        const float*  bhh_l = bhh  + (size_t)l * GG;

        // xw = seq_in @ Wih^T + bih  (fp16 output)
        {
            dim3 grid(GG / 128, MT / 128);
            k_gemm_fp16<<<grid, 256, GEMM_SMEM>>>(seq_in, Wih_l, bih_l, xw, MT, GG, HH, 2);
        }
        k_reset<<<(BQ * HH + 255) / 256, 256>>>();
        {
            dim3 grid(HH / 16, BQ / 64);   // (32, 4) = 128 CTAs
            k_lstm_persist<<<grid, 512, PERSIST_SMEM>>>(xw, Whh_l, bhh_l, seq_out,
                                                        (l == 0) ? 1 : 0);
        }
        const __half* tmp_in = seq_out;
        seq_out = (__half*)seq_in;
        seq_in  = tmp_in;
    }

    k_head<<<(BQ * 560 + 255) / 256, 256>>>(seq_in, W_out, b_out, W_cls, b_cls, out);
}